// round 6
// baseline (speedup 1.0000x reference)
#include <cuda_runtime.h>
#include <cuda_bf16.h>
#include <cstdint>
#include <cstddef>

#define TT 256
#define BB 32
#define HH 256
#define LL 4
#define VV 32000
#define HB (HH*BB)

#define NSLC 16               // slices per layer
#define RNN_CTAS (LL*NSLC)    // 64
#define JPS (HH/NSLC)         // 16 neurons per slice

#define DK   768
#define DBM  128
#define DBN  256
#define DBK  64
#define KITERS (DK/DBK)       // 12
#define MT (8192/DBM)         // 64
#define NT (VV/DBN)           // 125

// ---------------- device scratch ----------------
__device__ float g_h[LL][(size_t)(TT+1)*HB];          // [l][t][k][b]; t=0 row stays zero
__device__ unsigned g_flag[LL][TT+1][NSLC][8];        // padded 32B/slice; reset by cleanup
__device__ __nv_bfloat16 g_Bext[(size_t)VV*DK];       // [hi | hi | lo] per vocab row

// ---------------- helpers ----------------
__device__ __forceinline__ uint32_t smem_u32(const void* p) {
    uint32_t a;
    asm("{ .reg .u64 t; cvta.to.shared.u64 t, %1; cvt.u32.u64 %0, t; }" : "=r"(a) : "l"(p));
    return a;
}
#define CP_ASYNC16(dst, src) asm volatile("cp.async.cg.shared.global [%0], [%1], 16;" :: "r"(dst), "l"(src))
#define CP_COMMIT()          asm volatile("cp.async.commit_group;" ::: "memory")
#define CP_WAIT(n)           asm volatile("cp.async.wait_group %0;" :: "n"(n) : "memory")
#define LDSM4(r0,r1,r2,r3,addr) \
    asm volatile("ldmatrix.sync.aligned.m8n8.x4.shared.b16 {%0,%1,%2,%3}, [%4];" \
                 : "=r"(r0),"=r"(r1),"=r"(r2),"=r"(r3) : "r"(addr))
#define MMA16816(d, a, b0, b1) \
    asm volatile("mma.sync.aligned.m16n8k16.row.col.f32.bf16.bf16.f32 " \
                 "{%0,%1,%2,%3},{%4,%5,%6,%7},{%8,%9},{%0,%1,%2,%3};" \
                 : "+f"((d)[0]),"+f"((d)[1]),"+f"((d)[2]),"+f"((d)[3]) \
                 : "r"((a)[0]),"r"((a)[1]),"r"((a)[2]),"r"((a)[3]), "r"(b0),"r"(b1))

__device__ __forceinline__ void pollflag(const unsigned* p) {
    unsigned v;
    do { asm volatile("ld.global.acquire.gpu.u32 %0, [%1];" : "=r"(v) : "l"(p)); } while (!v);
}

// f32x2
__device__ __forceinline__ unsigned long long pk2(float lo, float hi) {
    unsigned long long r;
    asm("mov.b64 %0, {%1, %2};" : "=l"(r) : "r"(__float_as_uint(lo)), "r"(__float_as_uint(hi)));
    return r;
}
__device__ __forceinline__ unsigned long long fma2(unsigned long long a, unsigned long long b,
                                                   unsigned long long c) {
    unsigned long long d;
    asm("fma.rn.f32x2 %0, %1, %2, %3;" : "=l"(d) : "l"(a), "l"(b), "l"(c));
    return d;
}
__device__ __forceinline__ float upks(unsigned long long v) {
    unsigned a, b;
    asm("mov.b64 {%0, %1}, %2;" : "=r"(a), "=r"(b) : "l"(v));
    return __uint_as_float(a) + __uint_as_float(b);
}

// ================= convW: build Bext [hi|hi|lo] =================
__global__ void __launch_bounds__(256) convW_kernel(const float* __restrict__ W) {
    const size_t stride = (size_t)gridDim.x * 256;
    for (size_t e = (size_t)blockIdx.x * 256 + threadIdx.x; e < (size_t)VV * HH; e += stride) {
        const int k = (int)(e & 255);
        const size_t v = e >> 8;
        float w = W[e];
        __nv_bfloat16 hi = __float2bfloat16(w);
        __nv_bfloat16 lo = __float2bfloat16(w - __bfloat162float(hi));
        __nv_bfloat16* row = g_Bext + v * DK;
        row[k] = hi; row[256 + k] = hi; row[512 + k] = lo;
    }
}

// ================= cleanup: zero flags after each call =================
__global__ void __launch_bounds__(256) clr_kernel() {
    unsigned* p = &g_flag[0][0][0][0];
    const int N = LL * (TT + 1) * NSLC * 8;
    for (int i = blockIdx.x * 256 + threadIdx.x; i < N; i += gridDim.x * 256) p[i] = 0u;
}

// ================= fused RNN + decoder =================
// blocks [0,64): RNN (layer l = bid/16, slice s = bid%16)
// blocks [64, 64+8000): decoder tile d = bid-64; mt = d/NT, nt = d%NT
// dynamic smem (dec view): A_hi 4x16KB @0, A_lo 4x16KB @64K, B 3x32KB @128K  => 229376 B
#define AHI_OFF 0
#define ALO_OFF 65536
#define BST_OFF 131072
#define SM_TOTAL (BST_OFF + 3*32768)

__global__ void __launch_bounds__(256, 1) fused_kernel(const int* __restrict__ tokens,
                                                       const float* __restrict__ emb,
                                                       const float* __restrict__ W_ih,
                                                       const float* __restrict__ W_hh,
                                                       const float* __restrict__ b_ih,
                                                       const float* __restrict__ b_hh,
                                                       const float* __restrict__ dec_b,
                                                       float* __restrict__ out,
                                                       float* out_hidden, int write_hidden) {
    extern __shared__ char smem[];
    const int tid = threadIdx.x;
    const int bid = blockIdx.x;

    if (bid < RNN_CTAS) {
        // ---------------- RNN block ----------------
        const int l = bid / NSLC, s = bid % NSLC;
        const int n0 = s * JPS;
        float* wih_s = (float*)smem;              // [JPS][HH]
        float* whh_s = wih_s + JPS * HH;
        float* part  = whh_s + JPS * HH;          // [8][JPS][32]
        float* bias_s = part + 8 * JPS * 32;

        for (int i = tid; i < JPS * HH; i += 256) {
            int j = i / HH, k = i % HH;
            wih_s[i] = W_ih[((size_t)l*HH + n0 + j)*HH + k];
            whh_s[i] = W_hh[((size_t)l*HH + n0 + j)*HH + k];
        }
        if (tid < JPS) bias_s[tid] = b_ih[l*HH + n0 + tid] + b_hh[l*HH + n0 + tid];
        __syncthreads();

        const int wi = tid >> 5, lane = tid & 31;
        const int b = lane, kb = wi * 32;

        for (int t = 0; t < TT; t++) {
            if (wi == 0 && lane < NSLC && t > 0)  pollflag(&g_flag[l][t][lane][0]);
            if (wi == 1 && lane < NSLC && l > 0)  pollflag(&g_flag[l-1][t+1][lane][0]);
            __syncthreads();

            const float* hp = g_h[l] + (size_t)t * HB;
            const float* xp;
            if (l == 0) xp = emb + (size_t)tokens[t*BB + b] * HH;
            else        xp = g_h[l-1] + (size_t)(t+1) * HB;

            unsigned long long acc[JPS];
            #pragma unroll
            for (int j = 0; j < JPS; j++) acc[j] = 0ull;
            #pragma unroll
            for (int kk = 0; kk < 32; kk += 2) {
                const int k = kb + kk;
                unsigned long long hv = pk2(hp[k*BB + b], hp[(k+1)*BB + b]);
                unsigned long long xv;
                if (l == 0) { float2 e = *(const float2*)(xp + k); xv = pk2(e.x, e.y); }
                else        xv = pk2(xp[k*BB + b], xp[(k+1)*BB + b]);
                #pragma unroll
                for (int j = 0; j < JPS; j++) {
                    float2 wh = *(const float2*)&whh_s[j*HH + k];
                    float2 wx = *(const float2*)&wih_s[j*HH + k];
                    acc[j] = fma2(hv, pk2(wh.x, wh.y), acc[j]);
                    acc[j] = fma2(xv, pk2(wx.x, wx.y), acc[j]);
                }
            }
            #pragma unroll
            for (int j = 0; j < JPS; j++) part[(wi*JPS + j)*32 + b] = upks(acc[j]);
            __syncthreads();
            #pragma unroll
            for (int jj = 0; jj < 2; jj++) {
                const int j = wi * 2 + jj;
                float p = bias_s[j];
                #pragma unroll
                for (int w2 = 0; w2 < 8; w2++) p += part[(w2*JPS + j)*32 + lane];
                g_h[l][(size_t)(t+1)*HB + (n0 + j)*BB + lane] = tanhf(p);
            }
            __syncthreads();
            if (tid == 0) {
                __threadfence();
                *(volatile unsigned*)&g_flag[l][t+1][s][0] = 1u;
            }
            __syncthreads();
        }

        if (write_hidden) {
            #pragma unroll
            for (int jj = 0; jj < 2; jj++) {
                const int j = wi * 2 + jj;
                out_hidden[(size_t)l*BB*HH + (size_t)lane*HH + (n0 + j)] =
                    g_h[l][(size_t)TT*HB + (n0 + j)*BB + lane];
            }
        }
        return;
    }

    // ---------------- decoder block ----------------
    const int d = bid - RNN_CTAS;
    const int mt = d / NT, nt = d % NT;
    const int m0 = mt * DBM, n0 = nt * DBN;
    const uint32_t sbase = smem_u32(smem);
    const int wid = tid >> 5, lane = tid & 31;
    const int wm = (wid & 1) * 64;
    const int wn = (wid >> 1) * 64;

    // prefetch first two B stages (independent of RNN)
    {
        #pragma unroll
        for (int st = 0; st < 2; st++) {
            const uint32_t smB = sbase + BST_OFF + st * 32768;
            #pragma unroll
            for (int i = 0; i < 8; i++) {
                int li = tid + i * 256;
                int row = li >> 3, c = li & 7;
                const void* src = (const void*)(g_Bext + (size_t)(n0 + row) * DK + st * DBK + c * 8);
                CP_ASYNC16(smB + row * 128 + ((c ^ (row & 7)) << 4), src);
            }
            CP_COMMIT();
        }
    }

    // wait for our 4 timesteps from the top layer
    if (tid < NSLC) pollflag(&g_flag[LL-1][mt*4 + 4][tid][0]);
    __syncthreads();

    // inline A conversion: g_h[3] fp32 -> bf16 hi/lo slabs in smem
    {
        const int b = tid & 31, kw = tid >> 5;
        #pragma unroll
        for (int tp = 0; tp < 4; tp++) {
            const int r = tp * 32 + b;
            const float* src = g_h[LL-1] + (size_t)(mt*4 + tp + 1) * HB + b;
            #pragma unroll
            for (int kk = 0; kk < 32; kk++) {
                const int k = kw * 32 + kk;
                float x = src[k * BB];
                __nv_bfloat16 hi = __float2bfloat16(x);
                __nv_bfloat16 lo = __float2bfloat16(x - __bfloat162float(hi));
                const int c = (k & 63) >> 3;
                const uint32_t off = (uint32_t)(k >> 6) * 16384 + r * 128 +
                                     ((c ^ (r & 7)) << 4) + (k & 7) * 2;
                *(__nv_bfloat16*)(smem + AHI_OFF + off) = hi;
                *(__nv_bfloat16*)(smem + ALO_OFF + off) = lo;
            }
        }
    }
    __syncthreads();

    float acc[4][8][4];
    #pragma unroll
    for (int i = 0; i < 4; i++)
        #pragma unroll
        for (int j = 0; j < 8; j++)
            #pragma unroll
            for (int q = 0; q < 4; q++) acc[i][j][q] = 0.f;

    #pragma unroll 1
    for (int kc = 0; kc < KITERS; kc++) {
        if (kc + 2 < KITERS) {
            const uint32_t smB = sbase + BST_OFF + ((kc + 2) % 3) * 32768;
            #pragma unroll
            for (int i = 0; i < 8; i++) {
                int li = tid + i * 256;
                int row = li >> 3, c = li & 7;
                const void* src = (const void*)(g_Bext + (size_t)(n0 + row) * DK + (kc + 2) * DBK + c * 8);
                CP_ASYNC16(smB + row * 128 + ((c ^ (row & 7)) << 4), src);
            }
            CP_COMMIT();
            CP_WAIT(2);
        } else if (kc + 1 < KITERS) {
            CP_WAIT(1);
        } else {
            CP_WAIT(0);
        }
        __syncthreads();

        const uint32_t sA = sbase + ((kc >= 4 && kc < 8) ? ALO_OFF : AHI_OFF) + (kc & 3) * 16384;
        const uint32_t sB = sbase + BST_OFF + (kc % 3) * 32768;
        #pragma unroll
        for (int k16 = 0; k16 < 4; k16++) {
            uint32_t afr[4][4], bfr[4][4];
            #pragma unroll
            for (int mf = 0; mf < 4; mf++) {
                int rg = wm + mf * 16 + (lane & 15);
                int ch = k16 * 2 + (lane >> 4);
                LDSM4(afr[mf][0], afr[mf][1], afr[mf][2], afr[mf][3],
                      sA + rg * 128 + ((ch ^ (rg & 7)) << 4));
            }
            #pragma unroll
            for (int nf = 0; nf < 4; nf++) {
                int nr = wn + nf * 16 + (lane & 7) + ((lane >> 4) << 3);
                int ch = k16 * 2 + ((lane >> 3) & 1);
                LDSM4(bfr[nf][0], bfr[nf][1], bfr[nf][2], bfr[nf][3],
                      sB + nr * 128 + ((ch ^ (nr & 7)) << 4));
            }
            #pragma unroll
            for (int mf = 0; mf < 4; mf++)
                #pragma unroll
                for (int nf = 0; nf < 4; nf++) {
                    MMA16816(acc[mf][nf*2],   afr[mf], bfr[nf][0], bfr[nf][1]);
                    MMA16816(acc[mf][nf*2+1], afr[mf], bfr[nf][2], bfr[nf][3]);
                }
        }
        __syncthreads();
    }

    #pragma unroll
    for (int mf = 0; mf < 4; mf++) {
        const int r0 = m0 + wm + mf * 16 + (lane >> 2);
        #pragma unroll
        for (int nb = 0; nb < 8; nb++) {
            const int col = n0 + wn + nb * 8 + (lane & 3) * 2;
            float2 bb = *(const float2*)&dec_b[col];
            float2 s0 = { acc[mf][nb][0] + bb.x, acc[mf][nb][1] + bb.y };
            float2 s1 = { acc[mf][nb][2] + bb.x, acc[mf][nb][3] + bb.y };
            *(float2*)&out[(size_t)r0 * VV + col]       = s0;
            *(float2*)&out[(size_t)(r0 + 8) * VV + col] = s1;
        }
    }
}

extern "C" void kernel_launch(void* const* d_in, const int* in_sizes, int n_in,
                              void* d_out, int out_size) {
    const int*   tokens = (const int*)  d_in[0];
    const float* emb    = (const float*)d_in[1];
    const float* W_ih   = (const float*)d_in[2];
    const float* W_hh   = (const float*)d_in[3];
    const float* b_ih   = (const float*)d_in[4];
    const float* b_hh   = (const float*)d_in[5];
    const float* dec_W  = (const float*)d_in[6];
    const float* dec_b  = (const float*)d_in[7];
    float* out = (float*)d_out;

    const size_t dec_elems = (size_t)TT * BB * VV;
    const int write_hidden = ((size_t)out_size >= dec_elems + (size_t)LL*BB*HH) ? 1 : 0;
    float* out_hidden = out + dec_elems;

    cudaFuncSetAttribute(fused_kernel, cudaFuncAttributeMaxDynamicSharedMemorySize, SM_TOTAL);

    convW_kernel<<<2048, 256>>>(dec_W);
    fused_kernel<<<RNN_CTAS + MT * NT, 256, SM_TOTAL>>>(tokens, emb, W_ih, W_hh, b_ih, b_hh,
                                                        dec_b, out, out_hidden, write_hidden);
    clr_kernel<<<64, 256>>>();
}

// round 7
// speedup vs baseline: 1.1414x; 1.1414x over previous
#include <cuda_runtime.h>
#include <cuda_bf16.h>
#include <cstdint>
#include <cstddef>

#define TT 256
#define BB 32
#define HH 256
#define LL 4
#define VV 32000
#define HB (HH*BB)
#define NCTA 128
#define NSLC 32

#define DK   768
#define DBM  128
#define DBN  256
#define DBK  64
#define KITERS (DK/DBK)
#define MT (8192/DBM)
#define NT (VV/DBN)

// ---------------- device scratch ----------------
__device__ float g_h[LL][(size_t)(TT+1)*HB];      // [l][t][k][b]; t=0 row stays zero
__device__ unsigned g_flag[LL][TT+1][NSLC][8];    // one 32B sector per producer slice
__device__ __nv_bfloat16 g_Aext[(size_t)8192*DK];
__device__ __nv_bfloat16 g_Bext[(size_t)VV*DK];

// ---------------- helpers ----------------
__device__ __forceinline__ uint32_t smem_u32(const void* p) {
    uint32_t a;
    asm("{ .reg .u64 t; cvta.to.shared.u64 t, %1; cvt.u32.u64 %0, t; }" : "=r"(a) : "l"(p));
    return a;
}
#define CP_ASYNC16(dst, src) asm volatile("cp.async.cg.shared.global [%0], [%1], 16;" :: "r"(dst), "l"(src))
#define CP_COMMIT()          asm volatile("cp.async.commit_group;" ::: "memory")
#define CP_WAIT(n)           asm volatile("cp.async.wait_group %0;" :: "n"(n) : "memory")
#define LDSM4(r0,r1,r2,r3,addr) \
    asm volatile("ldmatrix.sync.aligned.m8n8.x4.shared.b16 {%0,%1,%2,%3}, [%4];" \
                 : "=r"(r0),"=r"(r1),"=r"(r2),"=r"(r3) : "r"(addr))
#define MMA16816(d, a, b0, b1) \
    asm volatile("mma.sync.aligned.m16n8k16.row.col.f32.bf16.bf16.f32 " \
                 "{%0,%1,%2,%3},{%4,%5,%6,%7},{%8,%9},{%0,%1,%2,%3};" \
                 : "+f"((d)[0]),"+f"((d)[1]),"+f"((d)[2]),"+f"((d)[3]) \
                 : "r"((a)[0]),"r"((a)[1]),"r"((a)[2]),"r"((a)[3]), "r"(b0),"r"(b1))

__device__ __forceinline__ void pollflag(const unsigned* p) {
    unsigned v;
    do { asm volatile("ld.global.acquire.gpu.u32 %0, [%1];" : "=r"(v) : "l"(p)); } while (!v);
}
__device__ __forceinline__ void setflag(unsigned* p) {
    asm volatile("st.global.release.gpu.u32 [%0], %1;" :: "l"(p), "r"(1u) : "memory");
}

// f32x2
__device__ __forceinline__ unsigned long long pk2(float lo, float hi) {
    unsigned long long r;
    asm("mov.b64 %0, {%1, %2};" : "=l"(r) : "r"(__float_as_uint(lo)), "r"(__float_as_uint(hi)));
    return r;
}
__device__ __forceinline__ unsigned long long fma2(unsigned long long a, unsigned long long b,
                                                   unsigned long long c) {
    unsigned long long d;
    asm("fma.rn.f32x2 %0, %1, %2, %3;" : "=l"(d) : "l"(a), "l"(b), "l"(c));
    return d;
}
__device__ __forceinline__ float upks(unsigned long long v) {
    unsigned a, b;
    asm("mov.b64 {%0, %1}, %2;" : "=r"(a), "=r"(b) : "l"(v));
    return __uint_as_float(a) + __uint_as_float(b);
}

// ================= conversions =================
__global__ void __launch_bounds__(256) convW_kernel(const float* __restrict__ W) {
    const size_t stride = (size_t)gridDim.x * 256;
    for (size_t e = (size_t)blockIdx.x * 256 + threadIdx.x; e < (size_t)VV * HH; e += stride) {
        const int k = (int)(e & 255);
        const size_t v = e >> 8;
        float w = W[e];
        __nv_bfloat16 hi = __float2bfloat16(w);
        __nv_bfloat16 lo = __float2bfloat16(w - __bfloat162float(hi));
        __nv_bfloat16* row = g_Bext + v * DK;
        row[k] = hi; row[256 + k] = hi; row[512 + k] = lo;
    }
}
__global__ void __launch_bounds__(256) convX_kernel() {
    const size_t stride = (size_t)gridDim.x * 256;
    for (size_t e = (size_t)blockIdx.x * 256 + threadIdx.x; e < (size_t)8192 * HH; e += stride) {
        const int m = (int)(e & 8191);
        const int k = (int)(e >> 13);
        const int t = m >> 5, b = m & 31;
        float x = g_h[LL-1][(size_t)(t + 1) * HB + k * BB + b];
        __nv_bfloat16 hi = __float2bfloat16(x);
        __nv_bfloat16 lo = __float2bfloat16(x - __bfloat162float(hi));
        __nv_bfloat16* row = g_Aext + (size_t)m * DK;
        row[k] = hi; row[256 + k] = lo; row[512 + k] = hi;
    }
}
__global__ void __launch_bounds__(256) clr_kernel() {
    unsigned* p = &g_flag[0][0][0][0];
    const int N = LL * (TT + 1) * NSLC * 8;
    for (int i = blockIdx.x * 256 + threadIdx.x; i < N; i += gridDim.x * 256) p[i] = 0u;
}

// ================= RNN: dataflow, spread flags, release/acquire =================
__global__ void __launch_bounds__(256) rnn_kernel(const int* __restrict__ tokens,
                                                  const float* __restrict__ emb,
                                                  const float* __restrict__ W_ih,
                                                  const float* __restrict__ W_hh,
                                                  const float* __restrict__ b_ih,
                                                  const float* __restrict__ b_hh,
                                                  float* out_hidden, int write_hidden) {
    const int cta = blockIdx.x;
    const int l = cta >> 5, s = cta & 31;
    const int n0 = s * 8;
    __shared__ float wih_s[8][HH], whh_s[8][HH];
    __shared__ float part[8][8][BB];
    __shared__ float bias_s[8];
    const int tid = threadIdx.x;

    for (int i = tid; i < 8*HH; i += 256) {
        int j = i / HH, k = i % HH;
        wih_s[j][k] = W_ih[((size_t)l*HH + n0 + j)*HH + k];
        whh_s[j][k] = W_hh[((size_t)l*HH + n0 + j)*HH + k];
    }
    if (tid < 8) bias_s[tid] = b_ih[l*HH + n0 + tid] + b_hh[l*HH + n0 + tid];
    __syncthreads();

    const int wi = tid >> 5, lane = tid & 31;
    const int b = lane, kb = wi * 32;

    for (int t = 0; t < TT; t++) {
        unsigned long long acc[8];
        #pragma unroll
        for (int j = 0; j < 8; j++) acc[j] = 0ull;

        // x-part for layer 0: independent of flags — do it before waiting
        if (l == 0) {
            const float* xp = emb + (size_t)tokens[t*BB + b] * HH;
            #pragma unroll
            for (int kk = 0; kk < 32; kk += 2) {
                const int k = kb + kk;
                float2 e = *(const float2*)(xp + k);
                unsigned long long xv = pk2(e.x, e.y);
                #pragma unroll
                for (int j = 0; j < 8; j++) {
                    float2 wx = *(const float2*)&wih_s[j][k];
                    acc[j] = fma2(xv, pk2(wx.x, wx.y), acc[j]);
                }
            }
        }

        // parallel flag waits: warp0 -> own layer h(t-1), warp1 -> lower layer x(t)
        if (t > 0 && wi == 0) pollflag(&g_flag[l][t][lane][0]);
        if (l > 0 && wi == 1) pollflag(&g_flag[l-1][t+1][lane][0]);
        __syncthreads();

        const float* hp = g_h[l] + (size_t)t * HB;
        #pragma unroll
        for (int kk = 0; kk < 32; kk += 2) {
            const int k = kb + kk;
            unsigned long long hv = pk2(hp[k*BB + b], hp[(k+1)*BB + b]);
            #pragma unroll
            for (int j = 0; j < 8; j++) {
                float2 wh = *(const float2*)&whh_s[j][k];
                acc[j] = fma2(hv, pk2(wh.x, wh.y), acc[j]);
            }
        }
        if (l > 0) {
            const float* xp = g_h[l-1] + (size_t)(t+1) * HB;
            #pragma unroll
            for (int kk = 0; kk < 32; kk += 2) {
                const int k = kb + kk;
                unsigned long long xv = pk2(xp[k*BB + b], xp[(k+1)*BB + b]);
                #pragma unroll
                for (int j = 0; j < 8; j++) {
                    float2 wx = *(const float2*)&wih_s[j][k];
                    acc[j] = fma2(xv, pk2(wx.x, wx.y), acc[j]);
                }
            }
        }
        #pragma unroll
        for (int j = 0; j < 8; j++) part[wi][j][b] = upks(acc[j]);
        __syncthreads();
        float p = bias_s[wi];
        #pragma unroll
        for (int w2 = 0; w2 < 8; w2++) p += part[w2][wi][b];
        g_h[l][(size_t)(t+1)*HB + (n0 + wi)*BB + b] = tanhf(p);
        __syncthreads();                 // all slice stores done; part reads done
        if (tid == 0) setflag(&g_flag[l][t+1][s][0]);   // release: orders CTA's h stores
    }

    if (write_hidden)
        out_hidden[(size_t)l*BB*HH + (size_t)b*HH + (n0 + wi)] =
            g_h[l][(size_t)TT*HB + (n0 + wi)*BB + b];
}

// ================= Decoder: mma.sync bf16 GEMM (K=768), 3-stage =================
#define STG_A 16384
#define STG_B 32768
#define STG   (STG_A + STG_B)
#define NSTG  3
#define SM_TOTAL (NSTG * STG)

__device__ __forceinline__ void load_stage(uint32_t smA, uint32_t smB, int kc,
                                           int m0, int n0, int tid) {
    #pragma unroll
    for (int i = 0; i < 4; i++) {
        int l = tid + i * 256;
        int row = l >> 3, c = l & 7;
        const void* src = (const void*)(g_Aext + (size_t)(m0 + row) * DK + kc * DBK + c * 8);
        CP_ASYNC16(smA + row * 128 + ((c ^ (row & 7)) << 4), src);
    }
    #pragma unroll
    for (int i = 0; i < 8; i++) {
        int l = tid + i * 256;
        int row = l >> 3, c = l & 7;
        const void* src = (const void*)(g_Bext + (size_t)(n0 + row) * DK + kc * DBK + c * 8);
        CP_ASYNC16(smB + row * 128 + ((c ^ (row & 7)) << 4), src);
    }
}

__global__ void __launch_bounds__(256, 1) dec_kernel(const float* __restrict__ dec_b,
                                                     float* __restrict__ out) {
    extern __shared__ char smem[];
    const uint32_t sbase = smem_u32(smem);
    const int tid = threadIdx.x;
    const int wid = tid >> 5, lane = tid & 31;
    const int m0 = blockIdx.x * DBM;
    const int n0 = blockIdx.y * DBN;
    const int wm = (wid & 1) * 64;
    const int wn = (wid >> 1) * 64;

    float acc[4][8][4];
    #pragma unroll
    for (int i = 0; i < 4; i++)
        #pragma unroll
        for (int j = 0; j < 8; j++)
            #pragma unroll
            for (int q = 0; q < 4; q++) acc[i][j][q] = 0.f;

    load_stage(sbase, sbase + STG_A, 0, m0, n0, tid);
    CP_COMMIT();
    load_stage(sbase + STG, sbase + STG + STG_A, 1, m0, n0, tid);
    CP_COMMIT();

    #pragma unroll 1
    for (int kc = 0; kc < KITERS; kc++) {
        if (kc + 2 < KITERS) {
            const uint32_t nA = sbase + ((kc + 2) % NSTG) * STG;
            load_stage(nA, nA + STG_A, kc + 2, m0, n0, tid);
            CP_COMMIT();
            CP_WAIT(2);
        } else if (kc + 1 < KITERS) {
            CP_WAIT(1);
        } else {
            CP_WAIT(0);
        }
        __syncthreads();

        const uint32_t sA = sbase + (kc % NSTG) * STG;
        const uint32_t sB = sA + STG_A;
        #pragma unroll
        for (int k16 = 0; k16 < 4; k16++) {
            uint32_t afr[4][4], bfr[4][4];
            #pragma unroll
            for (int mf = 0; mf < 4; mf++) {
                int rg = wm + mf * 16 + (lane & 15);
                int ch = k16 * 2 + (lane >> 4);
                LDSM4(afr[mf][0], afr[mf][1], afr[mf][2], afr[mf][3],
                      sA + rg * 128 + ((ch ^ (rg & 7)) << 4));
            }
            #pragma unroll
            for (int nf = 0; nf < 4; nf++) {
                int nr = wn + nf * 16 + (lane & 7) + ((lane >> 4) << 3);
                int ch = k16 * 2 + ((lane >> 3) & 1);
                LDSM4(bfr[nf][0], bfr[nf][1], bfr[nf][2], bfr[nf][3],
                      sB + nr * 128 + ((ch ^ (nr & 7)) << 4));
            }
            #pragma unroll
            for (int mf = 0; mf < 4; mf++)
                #pragma unroll
                for (int nf = 0; nf < 4; nf++) {
                    MMA16816(acc[mf][nf*2],   afr[mf], bfr[nf][0], bfr[nf][1]);
                    MMA16816(acc[mf][nf*2+1], afr[mf], bfr[nf][2], bfr[nf][3]);
                }
        }
        __syncthreads();
    }

    #pragma unroll
    for (int mf = 0; mf < 4; mf++) {
        const int r0 = m0 + wm + mf * 16 + (lane >> 2);
        #pragma unroll
        for (int nb = 0; nb < 8; nb++) {
            const int col = n0 + wn + nb * 8 + (lane & 3) * 2;
            float2 bb = *(const float2*)&dec_b[col];
            float2 s0 = { acc[mf][nb][0] + bb.x, acc[mf][nb][1] + bb.y };
            float2 s1 = { acc[mf][nb][2] + bb.x, acc[mf][nb][3] + bb.y };
            *(float2*)&out[(size_t)r0 * VV + col]       = s0;
            *(float2*)&out[(size_t)(r0 + 8) * VV + col] = s1;
        }
    }
}

extern "C" void kernel_launch(void* const* d_in, const int* in_sizes, int n_in,
                              void* d_out, int out_size) {
    const int*   tokens = (const int*)  d_in[0];
    const float* emb    = (const float*)d_in[1];
    const float* W_ih   = (const float*)d_in[2];
    const float* W_hh   = (const float*)d_in[3];
    const float* b_ih   = (const float*)d_in[4];
    const float* b_hh   = (const float*)d_in[5];
    const float* dec_W  = (const float*)d_in[6];
    const float* dec_b  = (const float*)d_in[7];
    float* out = (float*)d_out;

    const size_t dec_elems = (size_t)TT * BB * VV;
    const int write_hidden = ((size_t)out_size >= dec_elems + (size_t)LL*BB*HH) ? 1 : 0;
    float* out_hidden = out + dec_elems;

    cudaFuncSetAttribute(dec_kernel, cudaFuncAttributeMaxDynamicSharedMemorySize, SM_TOTAL);

    convW_kernel<<<2048, 256>>>(dec_W);
    rnn_kernel<<<NCTA, 256>>>(tokens, emb, W_ih, W_hh, b_ih, b_hh, out_hidden, write_hidden);
    clr_kernel<<<64, 256>>>();
    convX_kernel<<<512, 256>>>();
    dim3 grid(MT, NT);
    dec_kernel<<<grid, 256, SM_TOTAL>>>(dec_b, out);
}

// round 11
// speedup vs baseline: 1.2352x; 1.0822x over previous
#include <cuda_runtime.h>
#include <cuda_bf16.h>
#include <cstdint>
#include <cstddef>

#define TT 256
#define BB 32
#define HH 256
#define LL 4
#define VV 32000
#define HB (HH*BB)
#define NCTA 128

#define DK   768
#define DBM  128
#define DBN  256
#define DBK  64
#define KITERS (DK/DBK)
#define MT (8192/DBM)
#define NT (VV/DBN)

// ---------------- device scratch ----------------
__device__ float g_h[LL][(size_t)(TT+1)*HB];   // [l][t][k][b]; t=0 row stays zero
__device__ unsigned g_done[LL][TT+1];          // arrival counters, reset at kernel end
__device__ unsigned g_bar_count;
__device__ unsigned g_bar_gen;
__device__ __nv_bfloat16 g_Aext[(size_t)8192*DK];
__device__ __nv_bfloat16 g_Bext[(size_t)VV*DK];

// ---------------- helpers ----------------
__device__ __forceinline__ uint32_t smem_u32(const void* p) {
    uint32_t a;
    asm("{ .reg .u64 t; cvta.to.shared.u64 t, %1; cvt.u32.u64 %0, t; }" : "=r"(a) : "l"(p));
    return a;
}
#define CP_ASYNC16(dst, src) asm volatile("cp.async.cg.shared.global [%0], [%1], 16;" :: "r"(dst), "l"(src))
#define CP_COMMIT()          asm volatile("cp.async.commit_group;" ::: "memory")
#define CP_WAIT(n)           asm volatile("cp.async.wait_group %0;" :: "n"(n) : "memory")
#define LDSM4(r0,r1,r2,r3,addr) \
    asm volatile("ldmatrix.sync.aligned.m8n8.x4.shared.b16 {%0,%1,%2,%3}, [%4];" \
                 : "=r"(r0),"=r"(r1),"=r"(r2),"=r"(r3) : "r"(addr))
#define MMA16816(d, a, b0, b1) \
    asm volatile("mma.sync.aligned.m16n8k16.row.col.f32.bf16.bf16.f32 " \
                 "{%0,%1,%2,%3},{%4,%5,%6,%7},{%8,%9},{%0,%1,%2,%3};" \
                 : "+f"((d)[0]),"+f"((d)[1]),"+f"((d)[2]),"+f"((d)[3]) \
                 : "r"((a)[0]),"r"((a)[1]),"r"((a)[2]),"r"((a)[3]), "r"(b0),"r"(b1))

__device__ __forceinline__ void wait32(const unsigned* p) {
    unsigned v;
    do { asm volatile("ld.global.acquire.gpu.u32 %0, [%1];" : "=r"(v) : "l"(p)); } while (v < 32u);
}

// f32x2 helpers (RNN)
__device__ __forceinline__ unsigned long long pk2(float lo, float hi) {
    unsigned long long r;
    asm("mov.b64 %0, {%1, %2};" : "=l"(r) : "r"(__float_as_uint(lo)), "r"(__float_as_uint(hi)));
    return r;
}
__device__ __forceinline__ unsigned long long fma2(unsigned long long a, unsigned long long b,
                                                   unsigned long long c) {
    unsigned long long d;
    asm("fma.rn.f32x2 %0, %1, %2, %3;" : "=l"(d) : "l"(a), "l"(b), "l"(c));
    return d;
}
__device__ __forceinline__ float upks(unsigned long long v) {
    unsigned a, b;
    asm("mov.b64 {%0, %1}, %2;" : "=r"(a), "=r"(b) : "l"(v));
    return __uint_as_float(a) + __uint_as_float(b);
}

// ================= bf16-split conversions =================
__global__ void __launch_bounds__(256) convW_kernel(const float* __restrict__ W) {
    const size_t stride = (size_t)gridDim.x * 256;
    for (size_t e = (size_t)blockIdx.x * 256 + threadIdx.x; e < (size_t)VV * HH; e += stride) {
        const int k = (int)(e & 255);
        const size_t v = e >> 8;
        float w = W[e];
        __nv_bfloat16 hi = __float2bfloat16(w);
        __nv_bfloat16 lo = __float2bfloat16(w - __bfloat162float(hi));
        __nv_bfloat16* row = g_Bext + v * DK;
        row[k] = hi; row[256 + k] = hi; row[512 + k] = lo;
    }
}
__global__ void __launch_bounds__(256) convX_kernel() {
    const size_t stride = (size_t)gridDim.x * 256;
    for (size_t e = (size_t)blockIdx.x * 256 + threadIdx.x; e < (size_t)8192 * HH; e += stride) {
        const int m = (int)(e & 8191);
        const int k = (int)(e >> 13);
        const int t = m >> 5, b = m & 31;
        float x = g_h[LL-1][(size_t)(t + 1) * HB + k * BB + b];
        __nv_bfloat16 hi = __float2bfloat16(x);
        __nv_bfloat16 lo = __float2bfloat16(x - __bfloat162float(hi));
        __nv_bfloat16* row = g_Aext + (size_t)m * DK;
        row[k] = hi; row[256 + k] = lo; row[512 + k] = hi;
    }
}

// ================= RNN: dataflow (round-5 version, known-good) =================
__global__ void __launch_bounds__(256) rnn_kernel(const int* __restrict__ tokens,
                                                  const float* __restrict__ emb,
                                                  const float* __restrict__ W_ih,
                                                  const float* __restrict__ W_hh,
                                                  const float* __restrict__ b_ih,
                                                  const float* __restrict__ b_hh,
                                                  float* out_hidden, int write_hidden) {
    const int cta = blockIdx.x;
    const int l = cta >> 5;
    const int n0 = (cta & 31) * 8;
    __shared__ float wih_s[8][HH], whh_s[8][HH];
    __shared__ float part[8][8][BB];
    __shared__ float bias_s[8];
    const int tid = threadIdx.x;

    for (int i = tid; i < 8*HH; i += 256) {
        int j = i / HH, k = i % HH;
        wih_s[j][k] = W_ih[((size_t)l*HH + n0 + j)*HH + k];
        whh_s[j][k] = W_hh[((size_t)l*HH + n0 + j)*HH + k];
    }
    if (tid < 8) bias_s[tid] = b_ih[l*HH + n0 + tid] + b_hh[l*HH + n0 + tid];
    __syncthreads();

    const int wi = tid >> 5, b = tid & 31;
    const int kb = wi * 32;

    for (int t = 0; t < TT; t++) {
        if (t > 0) wait32(&g_done[l][t]);
        if (l > 0) wait32(&g_done[l-1][t+1]);

        const float* hp = g_h[l] + (size_t)t * HB;
        const float* xp;
        if (l == 0) xp = emb + (size_t)tokens[t*BB + b] * HH;
        else        xp = g_h[l-1] + (size_t)(t+1) * HB;
        unsigned long long acc[8];
        #pragma unroll
        for (int j = 0; j < 8; j++) acc[j] = 0ull;
        #pragma unroll
        for (int kk = 0; kk < 32; kk += 2) {
            const int k = kb + kk;
            unsigned long long hv = pk2(hp[k*BB + b], hp[(k+1)*BB + b]);
            unsigned long long xv;
            if (l == 0) { float2 e = *(const float2*)(xp + k); xv = pk2(e.x, e.y); }
            else        xv = pk2(xp[k*BB + b], xp[(k+1)*BB + b]);
            #pragma unroll
            for (int j = 0; j < 8; j++) {
                float2 wh = *(const float2*)&whh_s[j][k];
                float2 wx = *(const float2*)&wih_s[j][k];
                acc[j] = fma2(hv, pk2(wh.x, wh.y), acc[j]);
                acc[j] = fma2(xv, pk2(wx.x, wx.y), acc[j]);
            }
        }
        #pragma unroll
        for (int j = 0; j < 8; j++) part[wi][j][b] = upks(acc[j]);
        __syncthreads();
        float p = bias_s[wi];
        #pragma unroll
        for (int w2 = 0; w2 < 8; w2++) p += part[w2][wi][b];
        g_h[l][(size_t)(t+1)*HB + (n0 + wi)*BB + b] = tanhf(p);
        __syncthreads();
        if (tid == 0) {
            __threadfence();
            atomicAdd(&g_done[l][t+1], 1u);
        }
        __syncthreads();
    }

    if (write_hidden)
        out_hidden[(size_t)l*BB*HH + (size_t)b*HH + (n0 + wi)] =
            g_h[l][(size_t)TT*HB + (n0 + wi)*BB + b];

    // teardown: observe completion, barrier, reset counters
    wait32(&g_done[LL-1][TT]);
    __syncthreads();
    if (tid == 0) {
        unsigned gen = *(volatile unsigned*)&g_bar_gen;
        if (atomicAdd(&g_bar_count, 1u) == NCTA - 1u) {
            g_bar_count = 0u;
            __threadfence();
            atomicAdd(&g_bar_gen, 1u);
        } else {
            while (*(volatile unsigned*)&g_bar_gen == gen) { }
        }
        unsigned* cnt = &g_done[0][0];
        for (int i = cta; i < LL*(TT+1); i += NCTA) cnt[i] = 0u;
    }
}

// ================= Decoder: mma.sync bf16 GEMM (K=768), 512 threads, 2-stage =================
#define STG_A 16384
#define STG_B 32768
#define STG   (STG_A + STG_B)
#define SM_TOTAL (2 * STG)
#define DTHREADS 512

__device__ __forceinline__ void load_stage(uint32_t smA, uint32_t smB, int kc,
                                           int m0, int n0, int tid) {
    #pragma unroll
    for (int i = 0; i < 2; i++) {
        int l = tid + i * DTHREADS;
        int row = l >> 3, c = l & 7;
        const void* src = (const void*)(g_Aext + (size_t)(m0 + row) * DK + kc * DBK + c * 8);
        CP_ASYNC16(smA + row * 128 + ((c ^ (row & 7)) << 4), src);
    }
    #pragma unroll
    for (int i = 0; i < 4; i++) {
        int l = tid + i * DTHREADS;
        int row = l >> 3, c = l & 7;
        const void* src = (const void*)(g_Bext + (size_t)(n0 + row) * DK + kc * DBK + c * 8);
        CP_ASYNC16(smB + row * 128 + ((c ^ (row & 7)) << 4), src);
    }
}

__global__ void __launch_bounds__(DTHREADS, 1) dec_kernel(const float* __restrict__ dec_b,
                                                          float* __restrict__ out) {
    extern __shared__ char smem[];
    const uint32_t sbase = smem_u32(smem);
    const int tid = threadIdx.x;
    const int wid = tid >> 5, lane = tid & 31;
    const int m0 = blockIdx.x * DBM;
    const int n0 = blockIdx.y * DBN;
    const int wm = (wid & 1) * 64;        // 2 M-groups of 64
    const int wn = (wid >> 1) * 32;       // 8 N-groups of 32

    float acc[4][4][4];
    #pragma unroll
    for (int i = 0; i < 4; i++)
        #pragma unroll
        for (int j = 0; j < 4; j++)
            #pragma unroll
            for (int q = 0; q < 4; q++) acc[i][j][q] = 0.f;

    load_stage(sbase, sbase + STG_A, 0, m0, n0, tid);
    CP_COMMIT();

    #pragma unroll 1
    for (int kc = 0; kc < KITERS; kc++) {
        if (kc + 1 < KITERS) {
            const uint32_t nA = sbase + ((kc + 1) & 1) * STG;
            load_stage(nA, nA + STG_A, kc + 1, m0, n0, tid);
            CP_COMMIT();
            CP_WAIT(1);
        } else {
            CP_WAIT(0);
        }
        __syncthreads();

        const uint32_t sA = sbase + (kc & 1) * STG;
        const uint32_t sB = sA + STG_A;
        #pragma unroll
        for (int k16 = 0; k16 < 4; k16++) {
            uint32_t afr[4][4], bfr[2][4];
            #pragma unroll
            for (int mf = 0; mf < 4; mf++) {
                int rg = wm + mf * 16 + (lane & 15);
                int ch = k16 * 2 + (lane >> 4);
                LDSM4(afr[mf][0], afr[mf][1], afr[mf][2], afr[mf][3],
                      sA + rg * 128 + ((ch ^ (rg & 7)) << 4));
            }
            #pragma unroll
            for (int nf = 0; nf < 2; nf++) {
                int nr = wn + nf * 16 + (lane & 7) + ((lane >> 4) << 3);
                int ch = k16 * 2 + ((lane >> 3) & 1);
                LDSM4(bfr[nf][0], bfr[nf][1], bfr[nf][2], bfr[nf][3],
                      sB + nr * 128 + ((ch ^ (nr & 7)) << 4));
            }
            #pragma unroll
            for (int mf = 0; mf < 4; mf++)
                #pragma unroll
                for (int nf = 0; nf < 2; nf++) {
                    MMA16816(acc[mf][nf*2],   afr[mf], bfr[nf][0], bfr[nf][1]);
                    MMA16816(acc[mf][nf*2+1], afr[mf], bfr[nf][2], bfr[nf][3]);
                }
        }
        __syncthreads();
    }

    #pragma unroll
    for (int mf = 0; mf < 4; mf++) {
        const int r0 = m0 + wm + mf * 16 + (lane >> 2);
        #pragma unroll
        for (int nb = 0; nb < 4; nb++) {
            const int col = n0 + wn + nb * 8 + (lane & 3) * 2;
            float2 bb = *(const float2*)&dec_b[col];
            float2 s0 = { acc[mf][nb][0] + bb.x, acc[mf][nb][1] + bb.y };
            float2 s1 = { acc[mf][nb][2] + bb.x, acc[mf][nb][3] + bb.y };
            *(float2*)&out[(size_t)r0 * VV + col]       = s0;
            *(float2*)&out[(size_t)(r0 + 8) * VV + col] = s1;
        }
    }
}

extern "C" void kernel_launch(void* const* d_in, const int* in_sizes, int n_in,
                              void* d_out, int out_size) {
    const int*   tokens = (const int*)  d_in[0];
    const float* emb    = (const float*)d_in[1];
    const float* W_ih   = (const float*)d_in[2];
    const float* W_hh   = (const float*)d_in[3];
    const float* b_ih   = (const float*)d_in[4];
    const float* b_hh   = (const float*)d_in[5];
    const float* dec_W  = (const float*)d_in[6];
    const float* dec_b  = (const float*)d_in[7];
    float* out = (float*)d_out;

    const size_t dec_elems = (size_t)TT * BB * VV;
    const int write_hidden = ((size_t)out_size >= dec_elems + (size_t)LL*BB*HH) ? 1 : 0;
    float* out_hidden = out + dec_elems;

    cudaFuncSetAttribute(dec_kernel, cudaFuncAttributeMaxDynamicSharedMemorySize, SM_TOTAL);

    convW_kernel<<<2048, 256>>>(dec_W);
    rnn_kernel<<<NCTA, 256>>>(tokens, emb, W_ih, W_hh, b_ih, b_hh, out_hidden, write_hidden);
    convX_kernel<<<512, 256>>>();
    dim3 grid(MT, NT);
    dec_kernel<<<grid, DTHREADS, SM_TOTAL>>>(dec_b, out);
}

// round 12
// speedup vs baseline: 1.4055x; 1.1379x over previous
#include <cuda_runtime.h>
#include <cuda_fp16.h>
#include <cuda_bf16.h>
#include <cstdint>
#include <cstddef>

#define TT 256
#define BB 32
#define HH 256
#define LL 4
#define VV 32000
#define HB (HH*BB)
#define NCTA 128

#define DK   512          // fp16 2-term: A=[Xhi|Xhi], B=[Whi|Wlo]
#define DBM  128
#define DBN  256
#define DBK  64
#define KITERS (DK/DBK)   // 8
#define MT (8192/DBM)
#define NT (VV/DBN)

// ---------------- device scratch ----------------
__device__ float g_h[LL][(size_t)(TT+1)*HB];   // [l][t][k][b]; t=0 row stays zero
__device__ unsigned g_done[LL][TT+1];
__device__ unsigned g_bar_count;
__device__ unsigned g_bar_gen;
__device__ __half g_Aext[(size_t)8192*DK];     // 8.4 MB
__device__ __half g_Bext[(size_t)VV*DK];       // 32.8 MB

// ---------------- helpers ----------------
__device__ __forceinline__ uint32_t smem_u32(const void* p) {
    uint32_t a;
    asm("{ .reg .u64 t; cvta.to.shared.u64 t, %1; cvt.u32.u64 %0, t; }" : "=r"(a) : "l"(p));
    return a;
}
#define CP_ASYNC16(dst, src) asm volatile("cp.async.cg.shared.global [%0], [%1], 16;" :: "r"(dst), "l"(src))
#define CP_COMMIT()          asm volatile("cp.async.commit_group;" ::: "memory")
#define CP_WAIT(n)           asm volatile("cp.async.wait_group %0;" :: "n"(n) : "memory")
#define LDSM4(r0,r1,r2,r3,addr) \
    asm volatile("ldmatrix.sync.aligned.m8n8.x4.shared.b16 {%0,%1,%2,%3}, [%4];" \
                 : "=r"(r0),"=r"(r1),"=r"(r2),"=r"(r3) : "r"(addr))
#define MMA16816(d, a, b0, b1) \
    asm volatile("mma.sync.aligned.m16n8k16.row.col.f32.f16.f16.f32 " \
                 "{%0,%1,%2,%3},{%4,%5,%6,%7},{%8,%9},{%0,%1,%2,%3};" \
                 : "+f"((d)[0]),"+f"((d)[1]),"+f"((d)[2]),"+f"((d)[3]) \
                 : "r"((a)[0]),"r"((a)[1]),"r"((a)[2]),"r"((a)[3]), "r"(b0),"r"(b1))

__device__ __forceinline__ void wait32(const unsigned* p) {
    unsigned v;
    do { asm volatile("ld.global.acquire.gpu.u32 %0, [%1];" : "=r"(v) : "l"(p)); } while (v < 32u);
}

// f32x2 helpers (RNN)
__device__ __forceinline__ unsigned long long pk2(float lo, float hi) {
    unsigned long long r;
    asm("mov.b64 %0, {%1, %2};" : "=l"(r) : "r"(__float_as_uint(lo)), "r"(__float_as_uint(hi)));
    return r;
}
__device__ __forceinline__ unsigned long long fma2(unsigned long long a, unsigned long long b,
                                                   unsigned long long c) {
    unsigned long long d;
    asm("fma.rn.f32x2 %0, %1, %2, %3;" : "=l"(d) : "l"(a), "l"(b), "l"(c));
    return d;
}
__device__ __forceinline__ float upks(unsigned long long v) {
    unsigned a, b;
    asm("mov.b64 {%0, %1}, %2;" : "=r"(a), "=r"(b) : "l"(v));
    return __uint_as_float(a) + __uint_as_float(b);
}

// ================= conversions =================
__global__ void __launch_bounds__(256) convW_kernel(const float* __restrict__ W) {
    const size_t stride = (size_t)gridDim.x * 256;
    for (size_t e = (size_t)blockIdx.x * 256 + threadIdx.x; e < (size_t)VV * HH; e += stride) {
        const int k = (int)(e & 255);
        const size_t v = e >> 8;
        float w = W[e];
        __half hi = __float2half(w);
        __half lo = __float2half(w - __half2float(hi));
        __half* row = g_Bext + v * DK;
        row[k] = hi; row[256 + k] = lo;
    }
}
__global__ void __launch_bounds__(256) convX_kernel() {
    const size_t stride = (size_t)gridDim.x * 256;
    for (size_t e = (size_t)blockIdx.x * 256 + threadIdx.x; e < (size_t)8192 * HH; e += stride) {
        const int m = (int)(e & 8191);
        const int k = (int)(e >> 13);
        const int t = m >> 5, b = m & 31;
        float x = g_h[LL-1][(size_t)(t + 1) * HB + k * BB + b];
        __half hi = __float2half(x);
        __half* row = g_Aext + (size_t)m * DK;
        row[k] = hi; row[256 + k] = hi;
    }
}

// ================= RNN: dataflow (round-5 version, known-good) =================
__global__ void __launch_bounds__(256) rnn_kernel(const int* __restrict__ tokens,
                                                  const float* __restrict__ emb,
                                                  const float* __restrict__ W_ih,
                                                  const float* __restrict__ W_hh,
                                                  const float* __restrict__ b_ih,
                                                  const float* __restrict__ b_hh,
                                                  float* out_hidden, int write_hidden) {
    const int cta = blockIdx.x;
    const int l = cta >> 5;
    const int n0 = (cta & 31) * 8;
    __shared__ float wih_s[8][HH], whh_s[8][HH];
    __shared__ float part[8][8][BB];
    __shared__ float bias_s[8];
    const int tid = threadIdx.x;

    for (int i = tid; i < 8*HH; i += 256) {
        int j = i / HH, k = i % HH;
        wih_s[j][k] = W_ih[((size_t)l*HH + n0 + j)*HH + k];
        whh_s[j][k] = W_hh[((size_t)l*HH + n0 + j)*HH + k];
    }
    if (tid < 8) bias_s[tid] = b_ih[l*HH + n0 + tid] + b_hh[l*HH + n0 + tid];
    __syncthreads();

    const int wi = tid >> 5, b = tid & 31;
    const int kb = wi * 32;

    for (int t = 0; t < TT; t++) {
        if (t > 0) wait32(&g_done[l][t]);
        if (l > 0) wait32(&g_done[l-1][t+1]);

        const float* hp = g_h[l] + (size_t)t * HB;
        const float* xp;
        if (l == 0) xp = emb + (size_t)tokens[t*BB + b] * HH;
        else        xp = g_h[l-1] + (size_t)(t+1) * HB;
        unsigned long long acc[8];
        #pragma unroll
        for (int j = 0; j < 8; j++) acc[j] = 0ull;
        #pragma unroll
        for (int kk = 0; kk < 32; kk += 2) {
            const int k = kb + kk;
            unsigned long long hv = pk2(hp[k*BB + b], hp[(k+1)*BB + b]);
            unsigned long long xv;
            if (l == 0) { float2 e = *(const float2*)(xp + k); xv = pk2(e.x, e.y); }
            else        xv = pk2(xp[k*BB + b], xp[(k+1)*BB + b]);
            #pragma unroll
            for (int j = 0; j < 8; j++) {
                float2 wh = *(const float2*)&whh_s[j][k];
                float2 wx = *(const float2*)&wih_s[j][k];
                acc[j] = fma2(hv, pk2(wh.x, wh.y), acc[j]);
                acc[j] = fma2(xv, pk2(wx.x, wx.y), acc[j]);
            }
        }
        #pragma unroll
        for (int j = 0; j < 8; j++) part[wi][j][b] = upks(acc[j]);
        __syncthreads();
        float p = bias_s[wi];
        #pragma unroll
        for (int w2 = 0; w2 < 8; w2++) p += part[w2][wi][b];
        g_h[l][(size_t)(t+1)*HB + (n0 + wi)*BB + b] = tanhf(p);
        __syncthreads();
        if (tid == 0) {
            __threadfence();
            atomicAdd(&g_done[l][t+1], 1u);
        }
        __syncthreads();
    }

    if (write_hidden)
        out_hidden[(size_t)l*BB*HH + (size_t)b*HH + (n0 + wi)] =
            g_h[l][(size_t)TT*HB + (n0 + wi)*BB + b];

    // teardown: observe completion, barrier, reset counters
    wait32(&g_done[LL-1][TT]);
    __syncthreads();
    if (tid == 0) {
        unsigned gen = *(volatile unsigned*)&g_bar_gen;
        if (atomicAdd(&g_bar_count, 1u) == NCTA - 1u) {
            g_bar_count = 0u;
            __threadfence();
            atomicAdd(&g_bar_gen, 1u);
        } else {
            while (*(volatile unsigned*)&g_bar_gen == gen) { }
        }
        unsigned* cnt = &g_done[0][0];
        for (int i = cta; i < LL*(TT+1); i += NCTA) cnt[i] = 0u;
    }
}

// ================= Decoder: mma.sync fp16 GEMM (K=512), 256 threads, 2-stage =================
#define STG_A 16384
#define STG_B 32768
#define STG   (STG_A + STG_B)
#define SM_TOTAL (2 * STG)

__device__ __forceinline__ void load_stage(uint32_t smA, uint32_t smB, int kc,
                                           int m0, int n0, int tid) {
    #pragma unroll
    for (int i = 0; i < 4; i++) {
        int l = tid + i * 256;
        int row = l >> 3, c = l & 7;
        const void* src = (const void*)(g_Aext + (size_t)(m0 + row) * DK + kc * DBK + c * 8);
        CP_ASYNC16(smA + row * 128 + ((c ^ (row & 7)) << 4), src);
    }
    #pragma unroll
    for (int i = 0; i < 8; i++) {
        int l = tid + i * 256;
        int row = l >> 3, c = l & 7;
        const void* src = (const void*)(g_Bext + (size_t)(n0 + row) * DK + kc * DBK + c * 8);
        CP_ASYNC16(smB + row * 128 + ((c ^ (row & 7)) << 4), src);
    }
}

__global__ void __launch_bounds__(256, 1) dec_kernel(const float* __restrict__ dec_b,
                                                     float* __restrict__ out) {
    extern __shared__ char smem[];
    const uint32_t sbase = smem_u32(smem);
    const int tid = threadIdx.x;
    const int wid = tid >> 5, lane = tid & 31;
    const int m0 = blockIdx.x * DBM;
    const int n0 = blockIdx.y * DBN;
    const int wm = (wid & 1) * 64;
    const int wn = (wid >> 1) * 64;

    float acc[4][8][4];
    #pragma unroll
    for (int i = 0; i < 4; i++)
        #pragma unroll
        for (int j = 0; j < 8; j++)
            #pragma unroll
            for (int q = 0; q < 4; q++) acc[i][j][q] = 0.f;

    load_stage(sbase, sbase + STG_A, 0, m0, n0, tid);
    CP_COMMIT();

    #pragma unroll 1
    for (int kc = 0; kc < KITERS; kc++) {
        if (kc + 1 < KITERS) {
            const uint32_t nA = sbase + ((kc + 1) & 1) * STG;
            load_stage(nA, nA + STG_A, kc + 1, m0, n0, tid);
            CP_COMMIT();
            CP_WAIT(1);
        } else {
            CP_WAIT(0);
        }
        __syncthreads();

        const uint32_t sA = sbase + (kc & 1) * STG;
        const uint32_t sB = sA + STG_A;
        #pragma unroll
        for (int k16 = 0; k16 < 4; k16++) {
            uint32_t afr[4][4], bfr[4][4];
            #pragma unroll
            for (int mf = 0; mf < 4; mf++) {
                int rg = wm + mf * 16 + (lane & 15);
                int ch = k16 * 2 + (lane >> 4);
                LDSM4(afr[mf][0], afr[mf][1], afr[mf][2], afr[mf][3],
                      sA + rg * 128 + ((ch ^ (rg & 7)) << 4));
            }
            #pragma unroll
            for (int nf = 0; nf < 4; nf++) {
                int nr = wn + nf * 16 + (lane & 7) + ((lane >> 4) << 3);
                int ch = k16 * 2 + ((lane >> 3) & 1);
                LDSM4(bfr[nf][0], bfr[nf][1], bfr[nf][2], bfr[nf][3],
                      sB + nr * 128 + ((ch ^ (nr & 7)) << 4));
            }
            #pragma unroll
            for (int mf = 0; mf < 4; mf++)
                #pragma unroll
                for (int nf = 0; nf < 4; nf++) {
                    MMA16816(acc[mf][nf*2],   afr[mf], bfr[nf][0], bfr[nf][1]);
                    MMA16816(acc[mf][nf*2+1], afr[mf], bfr[nf][2], bfr[nf][3]);
                }
        }
        __syncthreads();
    }

    #pragma unroll
    for (int mf = 0; mf < 4; mf++) {
        const int r0 = m0 + wm + mf * 16 + (lane >> 2);
        #pragma unroll
        for (int nb = 0; nb < 8; nb++) {
            const int col = n0 + wn + nb * 8 + (lane & 3) * 2;
            float2 bb = *(const float2*)&dec_b[col];
            float2 s0 = { acc[mf][nb][0] + bb.x, acc[mf][nb][1] + bb.y };
            float2 s1 = { acc[mf][nb][2] + bb.x, acc[mf][nb][3] + bb.y };
            *(float2*)&out[(size_t)r0 * VV + col]       = s0;
            *(float2*)&out[(size_t)(r0 + 8) * VV + col] = s1;
        }
    }
}

extern "C" void kernel_launch(void* const* d_in, const int* in_sizes, int n_in,
                              void* d_out, int out_size) {
    const int*   tokens = (const int*)  d_in[0];
    const float* emb    = (const float*)d_in[1];
    const float* W_ih   = (const float*)d_in[2];
    const float* W_hh   = (const float*)d_in[3];
    const float* b_ih   = (const float*)d_in[4];
    const float* b_hh   = (const float*)d_in[5];
    const float* dec_W  = (const float*)d_in[6];
    const float* dec_b  = (const float*)d_in[7];
    float* out = (float*)d_out;

    const size_t dec_elems = (size_t)TT * BB * VV;
    const int write_hidden = ((size_t)out_size >= dec_elems + (size_t)LL*BB*HH) ? 1 : 0;
    float* out_hidden = out + dec_elems;

    cudaFuncSetAttribute(dec_kernel, cudaFuncAttributeMaxDynamicSharedMemorySize, SM_TOTAL);

    convW_kernel<<<2048, 256>>>(dec_W);
    rnn_kernel<<<NCTA, 256>>>(tokens, emb, W_ih, W_hh, b_ih, b_hh, out_hidden, write_hidden);
    convX_kernel<<<512, 256>>>();
    dim3 grid(MT, NT);
    dec_kernel<<<grid, 256, SM_TOTAL>>>(dec_b, out);
}

// round 13
// speedup vs baseline: 1.5271x; 1.0865x over previous
#include <cuda_runtime.h>
#include <cuda_fp16.h>
#include <cstdint>
#include <cstddef>

#define TT 256
#define BB 32
#define HH 256
#define LL 4
#define VV 32000
#define HB (HH*BB)
#define NCTA 128

#define DK   256          // plain fp16 GEMM: A=Xhi, B=Whi
#define DBM  128
#define DBN  256
#define DBK  64
#define KITERS (DK/DBK)   // 4
#define MT (8192/DBM)
#define NT (VV/DBN)

// ---------------- device scratch ----------------
__device__ float g_h[LL][(size_t)(TT+1)*HB];   // [l][t][k][b]; t=0 row stays zero
__device__ unsigned g_cnt[LL][TT+1];           // producer arrival counters (RMW only)
__device__ unsigned g_rdy[LL][TT+1][8];        // ready flags, 32B padded (read-only polling)
__device__ unsigned g_bar_count;
__device__ unsigned g_bar_gen;
__device__ __half g_Aext[(size_t)8192*DK];     // 4.2 MB
__device__ __half g_Bext[(size_t)VV*DK];       // 16.4 MB

// ---------------- helpers ----------------
__device__ __forceinline__ uint32_t smem_u32(const void* p) {
    uint32_t a;
    asm("{ .reg .u64 t; cvta.to.shared.u64 t, %1; cvt.u32.u64 %0, t; }" : "=r"(a) : "l"(p));
    return a;
}
#define CP_ASYNC16(dst, src) asm volatile("cp.async.cg.shared.global [%0], [%1], 16;" :: "r"(dst), "l"(src))
#define CP_COMMIT()          asm volatile("cp.async.commit_group;" ::: "memory")
#define CP_WAIT(n)           asm volatile("cp.async.wait_group %0;" :: "n"(n) : "memory")
#define LDSM4(r0,r1,r2,r3,addr) \
    asm volatile("ldmatrix.sync.aligned.m8n8.x4.shared.b16 {%0,%1,%2,%3}, [%4];" \
                 : "=r"(r0),"=r"(r1),"=r"(r2),"=r"(r3) : "r"(addr))
#define MMA16816(d, a, b0, b1) \
    asm volatile("mma.sync.aligned.m16n8k16.row.col.f32.f16.f16.f32 " \
                 "{%0,%1,%2,%3},{%4,%5,%6,%7},{%8,%9},{%0,%1,%2,%3};" \
                 : "+f"((d)[0]),"+f"((d)[1]),"+f"((d)[2]),"+f"((d)[3]) \
                 : "r"((a)[0]),"r"((a)[1]),"r"((a)[2]),"r"((a)[3]), "r"(b0),"r"(b1))

__device__ __forceinline__ void pollrdy(const unsigned* p) {
    unsigned v;
    do { asm volatile("ld.global.acquire.gpu.u32 %0, [%1];" : "=r"(v) : "l"(p)); } while (!v);
}

// f32x2 helpers (RNN)
__device__ __forceinline__ unsigned long long pk2(float lo, float hi) {
    unsigned long long r;
    asm("mov.b64 %0, {%1, %2};" : "=l"(r) : "r"(__float_as_uint(lo)), "r"(__float_as_uint(hi)));
    return r;
}
__device__ __forceinline__ unsigned long long fma2(unsigned long long a, unsigned long long b,
                                                   unsigned long long c) {
    unsigned long long d;
    asm("fma.rn.f32x2 %0, %1, %2, %3;" : "=l"(d) : "l"(a), "l"(b), "l"(c));
    return d;
}
__device__ __forceinline__ float upks(unsigned long long v) {
    unsigned a, b;
    asm("mov.b64 {%0, %1}, %2;" : "=r"(a), "=r"(b) : "l"(v));
    return __uint_as_float(a) + __uint_as_float(b);
}

// ================= conversions =================
__global__ void __launch_bounds__(256) convW_kernel(const float* __restrict__ W) {
    const size_t stride = (size_t)gridDim.x * 256;
    for (size_t e = (size_t)blockIdx.x * 256 + threadIdx.x; e < (size_t)VV * HH; e += stride) {
        g_Bext[e] = __float2half(W[e]);
    }
}
__global__ void __launch_bounds__(256) convX_kernel() {
    const size_t stride = (size_t)gridDim.x * 256;
    for (size_t e = (size_t)blockIdx.x * 256 + threadIdx.x; e < (size_t)8192 * HH; e += stride) {
        const int m = (int)(e & 8191);
        const int k = (int)(e >> 13);
        const int t = m >> 5, b = m & 31;
        g_Aext[(size_t)m * DK + k] =
            __float2half(g_h[LL-1][(size_t)(t + 1) * HB + k * BB + b]);
    }
}

// ================= RNN: dataflow with decoupled counter/ready lines =================
__global__ void __launch_bounds__(256) rnn_kernel(const int* __restrict__ tokens,
                                                  const float* __restrict__ emb,
                                                  const float* __restrict__ W_ih,
                                                  const float* __restrict__ W_hh,
                                                  const float* __restrict__ b_ih,
                                                  const float* __restrict__ b_hh,
                                                  float* out_hidden, int write_hidden) {
    const int cta = blockIdx.x;
    const int l = cta >> 5;
    const int n0 = (cta & 31) * 8;
    __shared__ float wih_s[8][HH], whh_s[8][HH];
    __shared__ float part[8][8][BB];
    __shared__ float bias_s[8];
    const int tid = threadIdx.x;

    for (int i = tid; i < 8*HH; i += 256) {
        int j = i / HH, k = i % HH;
        wih_s[j][k] = W_ih[((size_t)l*HH + n0 + j)*HH + k];
        whh_s[j][k] = W_hh[((size_t)l*HH + n0 + j)*HH + k];
    }
    if (tid < 8) bias_s[tid] = b_ih[l*HH + n0 + tid] + b_hh[l*HH + n0 + tid];
    __syncthreads();

    const int wi = tid >> 5, b = tid & 31;
    const int kb = wi * 32;

    for (int t = 0; t < TT; t++) {
        if (t > 0) pollrdy(&g_rdy[l][t][0]);
        if (l > 0) pollrdy(&g_rdy[l-1][t+1][0]);

        const float* hp = g_h[l] + (size_t)t * HB;
        const float* xp;
        if (l == 0) xp = emb + (size_t)tokens[t*BB + b] * HH;
        else        xp = g_h[l-1] + (size_t)(t+1) * HB;
        unsigned long long acc[8];
        #pragma unroll
        for (int j = 0; j < 8; j++) acc[j] = 0ull;
        #pragma unroll
        for (int kk = 0; kk < 32; kk += 2) {
            const int k = kb + kk;
            unsigned long long hv = pk2(hp[k*BB + b], hp[(k+1)*BB + b]);
            unsigned long long xv;
            if (l == 0) { float2 e = *(const float2*)(xp + k); xv = pk2(e.x, e.y); }
            else        xv = pk2(xp[k*BB + b], xp[(k+1)*BB + b]);
            #pragma unroll
            for (int j = 0; j < 8; j++) {
                float2 wh = *(const float2*)&whh_s[j][k];
                float2 wx = *(const float2*)&wih_s[j][k];
                acc[j] = fma2(hv, pk2(wh.x, wh.y), acc[j]);
                acc[j] = fma2(xv, pk2(wx.x, wx.y), acc[j]);
            }
        }
        #pragma unroll
        for (int j = 0; j < 8; j++) part[wi][j][b] = upks(acc[j]);
        __syncthreads();
        float p = bias_s[wi];
        #pragma unroll
        for (int w2 = 0; w2 < 8; w2++) p += part[w2][wi][b];
        g_h[l][(size_t)(t+1)*HB + (n0 + wi)*BB + b] = tanhf(p);
        __syncthreads();                         // CTA's h stores done
        if (tid == 0) {
            unsigned old;
            asm volatile("atom.global.acq_rel.gpu.add.u32 %0, [%1], %2;"
                         : "=r"(old) : "l"(&g_cnt[l][t+1]), "r"(1u) : "memory");
            if (old == 31u)
                asm volatile("st.global.release.gpu.u32 [%0], %1;"
                             :: "l"(&g_rdy[l][t+1][0]), "r"(1u) : "memory");
        }
        __syncthreads();
    }

    if (write_hidden)
        out_hidden[(size_t)l*BB*HH + (size_t)b*HH + (n0 + wi)] =
            g_h[l][(size_t)TT*HB + (n0 + wi)*BB + b];

    // teardown: observe completion, barrier, reset counters+flags
    pollrdy(&g_rdy[LL-1][TT][0]);
    __syncthreads();
    if (tid == 0) {
        unsigned gen = *(volatile unsigned*)&g_bar_gen;
        if (atomicAdd(&g_bar_count, 1u) == NCTA - 1u) {
            g_bar_count = 0u;
            __threadfence();
            atomicAdd(&g_bar_gen, 1u);
        } else {
            while (*(volatile unsigned*)&g_bar_gen == gen) { }
        }
        unsigned* c = &g_cnt[0][0];
        for (int i = cta; i < LL*(TT+1); i += NCTA) c[i] = 0u;
        unsigned* r = &g_rdy[0][0][0];
        for (int i = cta; i < LL*(TT+1)*8; i += NCTA) r[i] = 0u;
    }
}

// ================= Decoder: mma.sync fp16 GEMM (K=256), 256 threads, 2-stage =================
#define STG_A 16384
#define STG_B 32768
#define STG   (STG_A + STG_B)
#define SM_TOTAL (2 * STG)

__device__ __forceinline__ void load_stage(uint32_t smA, uint32_t smB, int kc,
                                           int m0, int n0, int tid) {
    #pragma unroll
    for (int i = 0; i < 4; i++) {
        int l = tid + i * 256;
        int row = l >> 3, c = l & 7;
        const void* src = (const void*)(g_Aext + (size_t)(m0 + row) * DK + kc * DBK + c * 8);
        CP_ASYNC16(smA + row * 128 + ((c ^ (row & 7)) << 4), src);
    }
    #pragma unroll
    for (int i = 0; i < 8; i++) {
        int l = tid + i * 256;
        int row = l >> 3, c = l & 7;
        const void* src = (const void*)(g_Bext + (size_t)(n0 + row) * DK + kc * DBK + c * 8);
        CP_ASYNC16(smB + row * 128 + ((c ^ (row & 7)) << 4), src);
    }
}

__global__ void __launch_bounds__(256, 1) dec_kernel(const float* __restrict__ dec_b,
                                                     float* __restrict__ out) {
    extern __shared__ char smem[];
    const uint32_t sbase = smem_u32(smem);
    const int tid = threadIdx.x;
    const int wid = tid >> 5, lane = tid & 31;
    const int m0 = blockIdx.x * DBM;
    const int n0 = blockIdx.y * DBN;
    const int wm = (wid & 1) * 64;
    const int wn = (wid >> 1) * 64;

    float acc[4][8][4];
    #pragma unroll
    for (int i = 0; i < 4; i++)
        #pragma unroll
        for (int j = 0; j < 8; j++)
            #pragma unroll
            for (int q = 0; q < 4; q++) acc[i][j][q] = 0.f;

    load_stage(sbase, sbase + STG_A, 0, m0, n0, tid);
    CP_COMMIT();

    #pragma unroll 1
    for (int kc = 0; kc < KITERS; kc++) {
        if (kc + 1 < KITERS) {
            const uint32_t nA = sbase + ((kc + 1) & 1) * STG;
            load_stage(nA, nA + STG_A, kc + 1, m0, n0, tid);
            CP_COMMIT();
            CP_WAIT(1);
        } else {
            CP_WAIT(0);
        }
        __syncthreads();

        const uint32_t sA = sbase + (kc & 1) * STG;
        const uint32_t sB = sA + STG_A;
        #pragma unroll
        for (int k16 = 0; k16 < 4; k16++) {
            uint32_t afr[4][4], bfr[4][4];
            #pragma unroll
            for (int mf = 0; mf < 4; mf++) {
                int rg = wm + mf * 16 + (lane & 15);
                int ch = k16 * 2 + (lane >> 4);
                LDSM4(afr[mf][0], afr[mf][1], afr[mf][2], afr[mf][3],
                      sA + rg * 128 + ((ch ^ (rg & 7)) << 4));
            }
            #pragma unroll
            for (int nf = 0; nf < 4; nf++) {
                int nr = wn + nf * 16 + (lane & 7) + ((lane >> 4) << 3);
                int ch = k16 * 2 + ((lane >> 3) & 1);
                LDSM4(bfr[nf][0], bfr[nf][1], bfr[nf][2], bfr[nf][3],
                      sB + nr * 128 + ((ch ^ (nr & 7)) << 4));
            }
            #pragma unroll
            for (int mf = 0; mf < 4; mf++)
                #pragma unroll
                for (int nf = 0; nf < 4; nf++) {
                    MMA16816(acc[mf][nf*2],   afr[mf], bfr[nf][0], bfr[nf][1]);
                    MMA16816(acc[mf][nf*2+1], afr[mf], bfr[nf][2], bfr[nf][3]);
                }
        }
        __syncthreads();
    }

    #pragma unroll
    for (int mf = 0; mf < 4; mf++) {
        const int r0 = m0 + wm + mf * 16 + (lane >> 2);
        #pragma unroll
        for (int nb = 0; nb < 8; nb++) {
            const int col = n0 + wn + nb * 8 + (lane & 3) * 2;
            float2 bb = *(const float2*)&dec_b[col];
            float2 s0 = { acc[mf][nb][0] + bb.x, acc[mf][nb][1] + bb.y };
            float2 s1 = { acc[mf][nb][2] + bb.x, acc[mf][nb][3] + bb.y };
            *(float2*)&out[(size_t)r0 * VV + col]       = s0;
            *(float2*)&out[(size_t)(r0 + 8) * VV + col] = s1;
        }
    }
}

extern "C" void kernel_launch(void* const* d_in, const int* in_sizes, int n_in,
                              void* d_out, int out_size) {
    const int*   tokens = (const int*)  d_in[0];
    const float* emb    = (const float*)d_in[1];
    const float* W_ih   = (const float*)d_in[2];
    const float* W_hh   = (const float*)d_in[3];
    const float* b_ih   = (const float*)d_in[4];
    const float* b_hh   = (const float*)d_in[5];
    const float* dec_W  = (const float*)d_in[6];
    const float* dec_b  = (const float*)d_in[7];
    float* out = (float*)d_out;

    const size_t dec_elems = (size_t)TT * BB * VV;
    const int write_hidden = ((size_t)out_size >= dec_elems + (size_t)LL*BB*HH) ? 1 : 0;
    float* out_hidden = out + dec_elems;

    cudaFuncSetAttribute(dec_kernel, cudaFuncAttributeMaxDynamicSharedMemorySize, SM_TOTAL);

    convW_kernel<<<2048, 256>>>(dec_W);
    rnn_kernel<<<NCTA, 256>>>(tokens, emb, W_ih, W_hh, b_ih, b_hh, out_hidden, write_hidden);
    convX_kernel<<<512, 256>>>();
    dim3 grid(MT, NT);
    dec_kernel<<<grid, 256, SM_TOTAL>>>(dec_b, out);
}

// round 14
// speedup vs baseline: 1.6120x; 1.0556x over previous
#include <cuda_runtime.h>
#include <cuda_fp16.h>
#include <cstdint>
#include <cstddef>

#define TT 256
#define BB 32
#define HH 256
#define LL 4
#define VV 32000
#define HB (HH*BB)
#define NCTA 128

#define DK   256          // plain fp16 GEMM: A=Xhi, B=Whi
#define DBM  128
#define DBN  256
#define DBK  64
#define KITERS (DK/DBK)   // 4
#define MT (8192/DBM)
#define NT (VV/DBN)

// ---------------- device scratch ----------------
__device__ float g_h[LL][(size_t)(TT+1)*HB];   // [l][t][k][b]; t=0 row stays zero
__device__ float g_A0[(size_t)TT*HB];          // [t][n][b] = W_ih0 @ emb[tok] + b_ih0
__device__ unsigned g_done[LL][TT+1];
__device__ unsigned g_bar_count;
__device__ unsigned g_bar_gen;
__device__ __half g_Aext[(size_t)8192*DK];
__device__ __half g_Bext[(size_t)VV*DK];

// ---------------- helpers ----------------
__device__ __forceinline__ uint32_t smem_u32(const void* p) {
    uint32_t a;
    asm("{ .reg .u64 t; cvta.to.shared.u64 t, %1; cvt.u32.u64 %0, t; }" : "=r"(a) : "l"(p));
    return a;
}
#define CP_ASYNC16(dst, src) asm volatile("cp.async.cg.shared.global [%0], [%1], 16;" :: "r"(dst), "l"(src))
#define CP_COMMIT()          asm volatile("cp.async.commit_group;" ::: "memory")
#define CP_WAIT(n)           asm volatile("cp.async.wait_group %0;" :: "n"(n) : "memory")
#define LDSM4(r0,r1,r2,r3,addr) \
    asm volatile("ldmatrix.sync.aligned.m8n8.x4.shared.b16 {%0,%1,%2,%3}, [%4];" \
                 : "=r"(r0),"=r"(r1),"=r"(r2),"=r"(r3) : "r"(addr))
#define MMA16816(d, a, b0, b1) \
    asm volatile("mma.sync.aligned.m16n8k16.row.col.f32.f16.f16.f32 " \
                 "{%0,%1,%2,%3},{%4,%5,%6,%7},{%8,%9},{%0,%1,%2,%3};" \
                 : "+f"((d)[0]),"+f"((d)[1]),"+f"((d)[2]),"+f"((d)[3]) \
                 : "r"((a)[0]),"r"((a)[1]),"r"((a)[2]),"r"((a)[3]), "r"(b0),"r"(b1))

__device__ __forceinline__ void wait32(const unsigned* p) {
    unsigned v;
    do { asm volatile("ld.global.acquire.gpu.u32 %0, [%1];" : "=r"(v) : "l"(p)); } while (v < 32u);
}

// f32x2 helpers
__device__ __forceinline__ unsigned long long pk2(float lo, float hi) {
    unsigned long long r;
    asm("mov.b64 %0, {%1, %2};" : "=l"(r) : "r"(__float_as_uint(lo)), "r"(__float_as_uint(hi)));
    return r;
}
__device__ __forceinline__ unsigned long long fma2(unsigned long long a, unsigned long long b,
                                                   unsigned long long c) {
    unsigned long long d;
    asm("fma.rn.f32x2 %0, %1, %2, %3;" : "=l"(d) : "l"(a), "l"(b), "l"(c));
    return d;
}
__device__ __forceinline__ float upks(unsigned long long v) {
    unsigned a, b;
    asm("mov.b64 {%0, %1}, %2;" : "=r"(a), "=r"(b) : "l"(v));
    return __uint_as_float(a) + __uint_as_float(b);
}

// ================= conversions =================
__global__ void __launch_bounds__(256) convW_kernel(const float* __restrict__ W) {
    const size_t stride = (size_t)gridDim.x * 256;
    for (size_t e = (size_t)blockIdx.x * 256 + threadIdx.x; e < (size_t)VV * HH; e += stride)
        g_Bext[e] = __float2half(W[e]);
}
__global__ void __launch_bounds__(256) convX_kernel() {
    const size_t stride = (size_t)gridDim.x * 256;
    for (size_t e = (size_t)blockIdx.x * 256 + threadIdx.x; e < (size_t)8192 * HH; e += stride) {
        const int m = (int)(e & 8191);
        const int k = (int)(e >> 13);
        const int t = m >> 5, b = m & 31;
        g_Aext[(size_t)m * DK + k] =
            __float2half(g_h[LL-1][(size_t)(t + 1) * HB + k * BB + b]);
    }
}

// ================= A0 precompute: g_A0[t][n][b] = W_ih0 . emb[tok[t][b]] + b_ih0[n] =================
// grid (32 nslot, 256 t), 256 thr. emb rows staged in smem (coalesced reads, padded banks).
#define A0_SMEM ((8*256 + 256*33 + 8*8*32) * 4)
__global__ void __launch_bounds__(256) a0_kernel(const int* __restrict__ tokens,
                                                 const float* __restrict__ emb,
                                                 const float* __restrict__ W_ih,
                                                 const float* __restrict__ b_ih) {
    extern __shared__ float dsm[];
    float* ws   = dsm;               // [8][256]
    float* xs   = ws + 8*256;        // [256][33]  (xs[k][b], padded)
    float* part = xs + 256*33;       // [8][8][32]
    __shared__ int   tok_s[BB];
    __shared__ float bias_s[8];
    const int t = blockIdx.y, n0 = blockIdx.x * 8, tid = threadIdx.x;

    if (tid < BB) tok_s[tid] = tokens[t*BB + tid];
    if (tid < 8)  bias_s[tid] = b_ih[n0 + tid];
    for (int i = tid; i < 8*256; i += 256) ws[i] = W_ih[(size_t)(n0 + (i >> 8)) * HH + (i & 255)];
    __syncthreads();
    #pragma unroll 4
    for (int r = 0; r < BB; r++) {
        const float* x = emb + (size_t)tok_s[r] * HH;
        xs[tid*33 + r] = x[tid];                    // coalesced read, conflict-free write
    }
    __syncthreads();

    const int wi = tid >> 5, b = tid & 31, kb = wi * 32;
    unsigned long long acc[8];
    #pragma unroll
    for (int j = 0; j < 8; j++) acc[j] = 0ull;
    #pragma unroll
    for (int kk = 0; kk < 32; kk += 2) {
        const int k = kb + kk;
        unsigned long long xv = pk2(xs[k*33 + b], xs[(k+1)*33 + b]);
        #pragma unroll
        for (int j = 0; j < 8; j++)
            acc[j] = fma2(xv, pk2(ws[j*256 + k], ws[j*256 + k + 1]), acc[j]);
    }
    #pragma unroll
    for (int j = 0; j < 8; j++) part[(wi*8 + j)*32 + b] = upks(acc[j]);
    __syncthreads();
    float p = bias_s[wi];
    #pragma unroll
    for (int w2 = 0; w2 < 8; w2++) p += part[(w2*8 + wi)*32 + b];
    g_A0[(size_t)t*HB + (n0 + wi)*BB + b] = p;
}

// ================= RNN: dataflow, R5 handoff, A0-precomputed layer 0 =================
__global__ void __launch_bounds__(256) rnn_kernel(const float* __restrict__ W_ih,
                                                  const float* __restrict__ W_hh,
                                                  const float* __restrict__ b_ih,
                                                  const float* __restrict__ b_hh,
                                                  float* out_hidden, int write_hidden) {
    const int cta = blockIdx.x;
    const int l = cta >> 5;
    const int n0 = (cta & 31) * 8;
    __shared__ float wih_s[8][HH], whh_s[8][HH];
    __shared__ float part[8][8][BB];
    __shared__ float bias_s[8];
    const int tid = threadIdx.x;

    for (int i = tid; i < 8*HH; i += 256) {
        int j = i / HH, k = i % HH;
        wih_s[j][k] = W_ih[((size_t)l*HH + n0 + j)*HH + k];
        whh_s[j][k] = W_hh[((size_t)l*HH + n0 + j)*HH + k];
    }
    if (tid < 8) bias_s[tid] = (l == 0 ? 0.f : b_ih[l*HH + n0 + tid]) + b_hh[l*HH + n0 + tid];
    __syncthreads();

    const int wi = tid >> 5, b = tid & 31;
    const int kb = wi * 32;

    for (int t = 0; t < TT; t++) {
        // hoist A0 read (independent of h) before the waits
        float a0v = 0.f;
        if (l == 0) a0v = g_A0[(size_t)t*HB + (n0 + wi)*BB + b];

        if (t > 0) wait32(&g_done[l][t]);
        if (l > 0) wait32(&g_done[l-1][t+1]);

        const float* hp = g_h[l] + (size_t)t * HB;
        unsigned long long acc[8];
        #pragma unroll
        for (int j = 0; j < 8; j++) acc[j] = 0ull;

        if (l == 0) {
            #pragma unroll
            for (int kk = 0; kk < 32; kk += 2) {
                const int k = kb + kk;
                unsigned long long hv = pk2(hp[k*BB + b], hp[(k+1)*BB + b]);
                #pragma unroll
                for (int j = 0; j < 8; j++) {
                    float2 wh = *(const float2*)&whh_s[j][k];
                    acc[j] = fma2(hv, pk2(wh.x, wh.y), acc[j]);
                }
            }
        } else {
            const float* xp = g_h[l-1] + (size_t)(t+1) * HB;
            #pragma unroll
            for (int kk = 0; kk < 32; kk += 2) {
                const int k = kb + kk;
                unsigned long long hv = pk2(hp[k*BB + b], hp[(k+1)*BB + b]);
                unsigned long long xv = pk2(xp[k*BB + b], xp[(k+1)*BB + b]);
                #pragma unroll
                for (int j = 0; j < 8; j++) {
                    float2 wh = *(const float2*)&whh_s[j][k];
                    float2 wx = *(const float2*)&wih_s[j][k];
                    acc[j] = fma2(hv, pk2(wh.x, wh.y), acc[j]);
                    acc[j] = fma2(xv, pk2(wx.x, wx.y), acc[j]);
                }
            }
        }
        #pragma unroll
        for (int j = 0; j < 8; j++) part[wi][j][b] = upks(acc[j]);
        __syncthreads();
        float p = bias_s[wi] + a0v;
        #pragma unroll
        for (int w2 = 0; w2 < 8; w2++) p += part[w2][wi][b];
        g_h[l][(size_t)(t+1)*HB + (n0 + wi)*BB + b] = tanhf(p);
        __syncthreads();
        if (tid == 0) {
            __threadfence();
            atomicAdd(&g_done[l][t+1], 1u);
        }
        __syncthreads();
    }

    if (write_hidden)
        out_hidden[(size_t)l*BB*HH + (size_t)b*HH + (n0 + wi)] =
            g_h[l][(size_t)TT*HB + (n0 + wi)*BB + b];

    // teardown: observe completion, barrier, reset counters
    wait32(&g_done[LL-1][TT]);
    __syncthreads();
    if (tid == 0) {
        unsigned gen = *(volatile unsigned*)&g_bar_gen;
        if (atomicAdd(&g_bar_count, 1u) == NCTA - 1u) {
            g_bar_count = 0u;
            __threadfence();
            atomicAdd(&g_bar_gen, 1u);
        } else {
            while (*(volatile unsigned*)&g_bar_gen == gen) { }
        }
        unsigned* cnt = &g_done[0][0];
        for (int i = cta; i < LL*(TT+1); i += NCTA) cnt[i] = 0u;
    }
}

// ================= Decoder: mma.sync fp16 GEMM (K=256), 2-stage (unchanged) =================
#define STG_A 16384
#define STG_B 32768
#define STG   (STG_A + STG_B)
#define SM_TOTAL (2 * STG)

__device__ __forceinline__ void load_stage(uint32_t smA, uint32_t smB, int kc,
                                           int m0, int n0, int tid) {
    #pragma unroll
    for (int i = 0; i < 4; i++) {
        int l = tid + i * 256;
        int row = l >> 3, c = l & 7;
        const void* src = (const void*)(g_Aext + (size_t)(m0 + row) * DK + kc * DBK + c * 8);
        CP_ASYNC16(smA + row * 128 + ((c ^ (row & 7)) << 4), src);
    }
    #pragma unroll
    for (int i = 0; i < 8; i++) {
        int l = tid + i * 256;
        int row = l >> 3, c = l & 7;
        const void* src = (const void*)(g_Bext + (size_t)(n0 + row) * DK + kc * DBK + c * 8);
        CP_ASYNC16(smB + row * 128 + ((c ^ (row & 7)) << 4), src);
    }
}

__global__ void __launch_bounds__(256, 1) dec_kernel(const float* __restrict__ dec_b,
                                                     float* __restrict__ out) {
    extern __shared__ char smem[];
    const uint32_t sbase = smem_u32(smem);
    const int tid = threadIdx.x;
    const int wid = tid >> 5, lane = tid & 31;
    const int m0 = blockIdx.x * DBM;
    const int n0 = blockIdx.y * DBN;
    const int wm = (wid & 1) * 64;
    const int wn = (wid >> 1) * 64;

    float acc[4][8][4];
    #pragma unroll
    for (int i = 0; i < 4; i++)
        #pragma unroll
        for (int j = 0; j < 8; j++)
            #pragma unroll
            for (int q = 0; q < 4; q++) acc[i][j][q] = 0.f;

    load_stage(sbase, sbase + STG_A, 0, m0, n0, tid);
    CP_COMMIT();

    #pragma unroll 1
    for (int kc = 0; kc < KITERS; kc++) {
        if (kc + 1 < KITERS) {
            const uint32_t nA = sbase + ((kc + 1) & 1) * STG;
            load_stage(nA, nA + STG_A, kc + 1, m0, n0, tid);
            CP_COMMIT();
            CP_WAIT(1);
        } else {
            CP_WAIT(0);
        }
        __syncthreads();

        const uint32_t sA = sbase + (kc & 1) * STG;
        const uint32_t sB = sA + STG_A;
        #pragma unroll
        for (int k16 = 0; k16 < 4; k16++) {
            uint32_t afr[4][4], bfr[4][4];
            #pragma unroll
            for (int mf = 0; mf < 4; mf++) {
                int rg = wm + mf * 16 + (lane & 15);
                int ch = k16 * 2 + (lane >> 4);
                LDSM4(afr[mf][0], afr[mf][1], afr[mf][2], afr[mf][3],
                      sA + rg * 128 + ((ch ^ (rg & 7)) << 4));
            }
            #pragma unroll
            for (int nf = 0; nf < 4; nf++) {
                int nr = wn + nf * 16 + (lane & 7) + ((lane >> 4) << 3);
                int ch = k16 * 2 + ((lane >> 3) & 1);
                LDSM4(bfr[nf][0], bfr[nf][1], bfr[nf][2], bfr[nf][3],
                      sB + nr * 128 + ((ch ^ (nr & 7)) << 4));
            }
            #pragma unroll
            for (int mf = 0; mf < 4; mf++)
                #pragma unroll
                for (int nf = 0; nf < 4; nf++) {
                    MMA16816(acc[mf][nf*2],   afr[mf], bfr[nf][0], bfr[nf][1]);
                    MMA16816(acc[mf][nf*2+1], afr[mf], bfr[nf][2], bfr[nf][3]);
                }
        }
        __syncthreads();
    }

    #pragma unroll
    for (int mf = 0; mf < 4; mf++) {
        const int r0 = m0 + wm + mf * 16 + (lane >> 2);
        #pragma unroll
        for (int nb = 0; nb < 8; nb++) {
            const int col = n0 + wn + nb * 8 + (lane & 3) * 2;
            float2 bb = *(const float2*)&dec_b[col];
            float2 s0 = { acc[mf][nb][0] + bb.x, acc[mf][nb][1] + bb.y };
            float2 s1 = { acc[mf][nb][2] + bb.x, acc[mf][nb][3] + bb.y };
            *(float2*)&out[(size_t)r0 * VV + col]       = s0;
            *(float2*)&out[(size_t)(r0 + 8) * VV + col] = s1;
        }
    }
}

extern "C" void kernel_launch(void* const* d_in, const int* in_sizes, int n_in,
                              void* d_out, int out_size) {
    const int*   tokens = (const int*)  d_in[0];
    const float* emb    = (const float*)d_in[1];
    const float* W_ih   = (const float*)d_in[2];
    const float* W_hh   = (const float*)d_in[3];
    const float* b_ih   = (const float*)d_in[4];
    const float* b_hh   = (const float*)d_in[5];
    const float* dec_W  = (const float*)d_in[6];
    const float* dec_b  = (const float*)d_in[7];
    float* out = (float*)d_out;

    const size_t dec_elems = (size_t)TT * BB * VV;
    const int write_hidden = ((size_t)out_size >= dec_elems + (size_t)LL*BB*HH) ? 1 : 0;
    float* out_hidden = out + dec_elems;

    cudaFuncSetAttribute(dec_kernel, cudaFuncAttributeMaxDynamicSharedMemorySize, SM_TOTAL);
    cudaFuncSetAttribute(a0_kernel, cudaFuncAttributeMaxDynamicSharedMemorySize, A0_SMEM);

    convW_kernel<<<2048, 256>>>(dec_W);
    {
        dim3 ag(32, 256);
        a0_kernel<<<ag, 256, A0_SMEM>>>(tokens, emb, W_ih, b_ih);
    }
    rnn_kernel<<<NCTA, 256>>>(W_ih, W_hh, b_ih, b_hh, out_hidden, write_hidden);
    convX_kernel<<<512, 256>>>();
    dim3 grid(MT, NT);
    dec_kernel<<<grid, 256, SM_TOTAL>>>(dec_b, out);
}

// round 15
// speedup vs baseline: 2.4686x; 1.5315x over previous
#include <cuda_runtime.h>
#include <cuda_fp16.h>
#include <cstdint>
#include <cstddef>

#define TT 256
#define BB 32
#define HH 256
#define LL 4
#define VV 32000
#define HB (HH*BB)
#define NCTA 128

#define DK   256          // plain fp16 GEMM: A=Xhi, B=Whi
#define DBM  128
#define DBN  256
#define DBK  64
#define KITERS (DK/DBK)   // 4
#define MT (8192/DBM)     // 64
#define NT (VV/DBN)       // 125

// ---------------- device scratch ----------------
__device__ float g_h[LL][(size_t)(TT+1)*HB];   // [l][t][k][b]; t=0 row stays zero
__device__ float g_A0[(size_t)TT*HB];          // [t][n][b] = W_ih0 @ emb[tok] + b_ih0
__device__ unsigned g_done[LL][TT+1];          // arrival counters (cleared by clr_kernel)
__device__ __half g_Aext[(size_t)8192*DK];     // [m][k], written by layer-3 RNN CTAs
__device__ __half g_Bext[(size_t)VV*DK];

// ---------------- helpers ----------------
__device__ __forceinline__ uint32_t smem_u32(const void* p) {
    uint32_t a;
    asm("{ .reg .u64 t; cvta.to.shared.u64 t, %1; cvt.u32.u64 %0, t; }" : "=r"(a) : "l"(p));
    return a;
}
#define CP_ASYNC16(dst, src) asm volatile("cp.async.cg.shared.global [%0], [%1], 16;" :: "r"(dst), "l"(src))
#define CP_COMMIT()          asm volatile("cp.async.commit_group;" ::: "memory")
#define CP_WAIT(n)           asm volatile("cp.async.wait_group %0;" :: "n"(n) : "memory")
#define LDSM4(r0,r1,r2,r3,addr) \
    asm volatile("ldmatrix.sync.aligned.m8n8.x4.shared.b16 {%0,%1,%2,%3}, [%4];" \
                 : "=r"(r0),"=r"(r1),"=r"(r2),"=r"(r3) : "r"(addr))
#define MMA16816(d, a, b0, b1) \
    asm volatile("mma.sync.aligned.m16n8k16.row.col.f32.f16.f16.f32 " \
                 "{%0,%1,%2,%3},{%4,%5,%6,%7},{%8,%9},{%0,%1,%2,%3};" \
                 : "+f"((d)[0]),"+f"((d)[1]),"+f"((d)[2]),"+f"((d)[3]) \
                 : "r"((a)[0]),"r"((a)[1]),"r"((a)[2]),"r"((a)[3]), "r"(b0),"r"(b1))

__device__ __forceinline__ void wait32(const unsigned* p) {
    unsigned v;
    do { asm volatile("ld.global.acquire.gpu.u32 %0, [%1];" : "=r"(v) : "l"(p)); } while (v < 32u);
}

// f32x2 helpers
__device__ __forceinline__ unsigned long long pk2(float lo, float hi) {
    unsigned long long r;
    asm("mov.b64 %0, {%1, %2};" : "=l"(r) : "r"(__float_as_uint(lo)), "r"(__float_as_uint(hi)));
    return r;
}
__device__ __forceinline__ unsigned long long fma2(unsigned long long a, unsigned long long b,
                                                   unsigned long long c) {
    unsigned long long d;
    asm("fma.rn.f32x2 %0, %1, %2, %3;" : "=l"(d) : "l"(a), "l"(b), "l"(c));
    return d;
}
__device__ __forceinline__ float upks(unsigned long long v) {
    unsigned a, b;
    asm("mov.b64 {%0, %1}, %2;" : "=r"(a), "=r"(b) : "l"(v));
    return __uint_as_float(a) + __uint_as_float(b);
}

// ================= convW =================
__global__ void __launch_bounds__(256) convW_kernel(const float* __restrict__ W) {
    const size_t stride = (size_t)gridDim.x * 256;
    for (size_t e = (size_t)blockIdx.x * 256 + threadIdx.x; e < (size_t)VV * HH; e += stride)
        g_Bext[e] = __float2half(W[e]);
}

// ================= A0 precompute =================
#define A0_SMEM ((8*256 + 256*33 + 8*8*32) * 4)
__global__ void __launch_bounds__(256) a0_kernel(const int* __restrict__ tokens,
                                                 const float* __restrict__ emb,
                                                 const float* __restrict__ W_ih,
                                                 const float* __restrict__ b_ih) {
    extern __shared__ float dsm[];
    float* ws   = dsm;               // [8][256]
    float* xs   = ws + 8*256;        // [256][33]
    float* part = xs + 256*33;       // [8][8][32]
    __shared__ int   tok_s[BB];
    __shared__ float bias_s[8];
    const int t = blockIdx.y, n0 = blockIdx.x * 8, tid = threadIdx.x;

    if (tid < BB) tok_s[tid] = tokens[t*BB + tid];
    if (tid < 8)  bias_s[tid] = b_ih[n0 + tid];
    for (int i = tid; i < 8*256; i += 256) ws[i] = W_ih[(size_t)(n0 + (i >> 8)) * HH + (i & 255)];
    __syncthreads();
    #pragma unroll 4
    for (int r = 0; r < BB; r++) {
        const float* x = emb + (size_t)tok_s[r] * HH;
        xs[tid*33 + r] = x[tid];
    }
    __syncthreads();

    const int wi = tid >> 5, b = tid & 31, kb = wi * 32;
    unsigned long long acc[8];
    #pragma unroll
    for (int j = 0; j < 8; j++) acc[j] = 0ull;
    #pragma unroll
    for (int kk = 0; kk < 32; kk += 2) {
        const int k = kb + kk;
        unsigned long long xv = pk2(xs[k*33 + b], xs[(k+1)*33 + b]);
        #pragma unroll
        for (int j = 0; j < 8; j++)
            acc[j] = fma2(xv, pk2(ws[j*256 + k], ws[j*256 + k + 1]), acc[j]);
    }
    #pragma unroll
    for (int j = 0; j < 8; j++) part[(wi*8 + j)*32 + b] = upks(acc[j]);
    __syncthreads();
    float p = bias_s[wi];
    #pragma unroll
    for (int w2 = 0; w2 < 8; w2++) p += part[(w2*8 + wi)*32 + b];
    g_A0[(size_t)t*HB + (n0 + wi)*BB + b] = p;
}

// ================= clr: reset counters after fused kernel =================
__global__ void __launch_bounds__(256) clr_kernel() {
    unsigned* p = &g_done[0][0];
    const int N = LL * (TT + 1);
    for (int i = blockIdx.x * 256 + threadIdx.x; i < N; i += gridDim.x * 256) p[i] = 0u;
}

// ================= fused RNN + decoder =================
// blocks [0,128): RNN (R14 logic).  blocks [128, 8128): dec tile d = bid-128 (mt-major).
#define STG_A 16384
#define STG_B 32768
#define STG   (STG_A + STG_B)
#define SM_TOTAL (2 * STG)

__device__ __forceinline__ void load_stage(uint32_t smA, uint32_t smB, int kc,
                                           int m0, int n0, int tid) {
    #pragma unroll
    for (int i = 0; i < 4; i++) {
        int l = tid + i * 256;
        int row = l >> 3, c = l & 7;
        const void* src = (const void*)(g_Aext + (size_t)(m0 + row) * DK + kc * DBK + c * 8);
        CP_ASYNC16(smA + row * 128 + ((c ^ (row & 7)) << 4), src);
    }
    #pragma unroll
    for (int i = 0; i < 8; i++) {
        int l = tid + i * 256;
        int row = l >> 3, c = l & 7;
        const void* src = (const void*)(g_Bext + (size_t)(n0 + row) * DK + kc * DBK + c * 8);
        CP_ASYNC16(smB + row * 128 + ((c ^ (row & 7)) << 4), src);
    }
}

__global__ void __launch_bounds__(256, 1) fused_kernel(const float* __restrict__ W_ih,
                                                       const float* __restrict__ W_hh,
                                                       const float* __restrict__ b_ih,
                                                       const float* __restrict__ b_hh,
                                                       const float* __restrict__ dec_b,
                                                       float* __restrict__ out,
                                                       float* out_hidden, int write_hidden) {
    extern __shared__ char smem[];
    const int tid = threadIdx.x;
    const int bid = blockIdx.x;

    if (bid < NCTA) {
        // ================ RNN block (R14 logic) ================
        const int l = bid >> 5;
        const int n0 = (bid & 31) * 8;
        float* wih_s  = (float*)smem;            // [8][256]
        float* whh_s  = wih_s + 8*HH;            // [8][256]
        float* part   = whh_s + 8*HH;            // [8][8][32]
        float* bias_s = part + 8*8*BB;           // [8]

        for (int i = tid; i < 8*HH; i += 256) {
            int j = i / HH, k = i % HH;
            wih_s[i] = W_ih[((size_t)l*HH + n0 + j)*HH + k];
            whh_s[i] = W_hh[((size_t)l*HH + n0 + j)*HH + k];
        }
        if (tid < 8) bias_s[tid] = (l == 0 ? 0.f : b_ih[l*HH + n0 + tid]) + b_hh[l*HH + n0 + tid];
        __syncthreads();

        const int wi = tid >> 5, b = tid & 31;
        const int kb = wi * 32;

        for (int t = 0; t < TT; t++) {
            float a0v = 0.f;
            if (l == 0) a0v = g_A0[(size_t)t*HB + (n0 + wi)*BB + b];

            if (t > 0) wait32(&g_done[l][t]);
            if (l > 0) wait32(&g_done[l-1][t+1]);

            const float* hp = g_h[l] + (size_t)t * HB;
            unsigned long long acc[8];
            #pragma unroll
            for (int j = 0; j < 8; j++) acc[j] = 0ull;

            if (l == 0) {
                #pragma unroll
                for (int kk = 0; kk < 32; kk += 2) {
                    const int k = kb + kk;
                    unsigned long long hv = pk2(hp[k*BB + b], hp[(k+1)*BB + b]);
                    #pragma unroll
                    for (int j = 0; j < 8; j++) {
                        float2 wh = *(const float2*)&whh_s[j*HH + k];
                        acc[j] = fma2(hv, pk2(wh.x, wh.y), acc[j]);
                    }
                }
            } else {
                const float* xp = g_h[l-1] + (size_t)(t+1) * HB;
                #pragma unroll
                for (int kk = 0; kk < 32; kk += 2) {
                    const int k = kb + kk;
                    unsigned long long hv = pk2(hp[k*BB + b], hp[(k+1)*BB + b]);
                    unsigned long long xv = pk2(xp[k*BB + b], xp[(k+1)*BB + b]);
                    #pragma unroll
                    for (int j = 0; j < 8; j++) {
                        float2 wh = *(const float2*)&whh_s[j*HH + k];
                        float2 wx = *(const float2*)&wih_s[j*HH + k];
                        acc[j] = fma2(hv, pk2(wh.x, wh.y), acc[j]);
                        acc[j] = fma2(xv, pk2(wx.x, wx.y), acc[j]);
                    }
                }
            }
            #pragma unroll
            for (int j = 0; j < 8; j++) part[(wi*8 + j)*32 + b] = upks(acc[j]);
            __syncthreads();
            float p = bias_s[wi] + a0v;
            #pragma unroll
            for (int w2 = 0; w2 < 8; w2++) p += part[(w2*8 + wi)*32 + b];
            float hv = tanhf(p);
            g_h[l][(size_t)(t+1)*HB + (n0 + wi)*BB + b] = hv;
            if (l == LL-1)   // fp16 A row for the decoder (m = t*32+b, k = n0+wi)
                g_Aext[(size_t)(t*BB + b)*DK + (n0 + wi)] = __float2half(hv);
            __syncthreads();
            if (tid == 0) {
                __threadfence();
                atomicAdd(&g_done[l][t+1], 1u);
            }
            __syncthreads();
        }

        if (write_hidden)
            out_hidden[(size_t)l*BB*HH + (size_t)b*HH + (n0 + wi)] =
                g_h[l][(size_t)TT*HB + (n0 + wi)*BB + b];
        return;
    }

    // ================ decoder block ================
    const int d = bid - NCTA;
    const int mt = d / NT, nt = d % NT;
    const int m0 = mt * DBM, n0 = nt * DBN;
    const uint32_t sbase = smem_u32(smem);
    const int wid = tid >> 5, lane = tid & 31;
    const int wm = (wid & 1) * 64;
    const int wn = (wid >> 1) * 64;

    // wait for our 4 timesteps of the top layer (monotone counter; cp.async.cg bypasses L1)
    if (tid == 0) wait32(&g_done[LL-1][mt*4 + 4]);
    __syncthreads();

    float acc[4][8][4];
    #pragma unroll
    for (int i = 0; i < 4; i++)
        #pragma unroll
        for (int j = 0; j < 8; j++)
            #pragma unroll
            for (int q = 0; q < 4; q++) acc[i][j][q] = 0.f;

    load_stage(sbase, sbase + STG_A, 0, m0, n0, tid);
    CP_COMMIT();

    #pragma unroll 1
    for (int kc = 0; kc < KITERS; kc++) {
        if (kc + 1 < KITERS) {
            const uint32_t nA = sbase + ((kc + 1) & 1) * STG;
            load_stage(nA, nA + STG_A, kc + 1, m0, n0, tid);
            CP_COMMIT();
            CP_WAIT(1);
        } else {
            CP_WAIT(0);
        }
        __syncthreads();

        const uint32_t sA = sbase + (kc & 1) * STG;
        const uint32_t sB = sA + STG_A;
        #pragma unroll
        for (int k16 = 0; k16 < 4; k16++) {
            uint32_t afr[4][4], bfr[4][4];
            #pragma unroll
            for (int mf = 0; mf < 4; mf++) {
                int rg = wm + mf * 16 + (lane & 15);
                int ch = k16 * 2 + (lane >> 4);
                LDSM4(afr[mf][0], afr[mf][1], afr[mf][2], afr[mf][3],
                      sA + rg * 128 + ((ch ^ (rg & 7)) << 4));
            }
            #pragma unroll
            for (int nf = 0; nf < 4; nf++) {
                int nr = wn + nf * 16 + (lane & 7) + ((lane >> 4) << 3);
                int ch = k16 * 2 + ((lane >> 3) & 1);
                LDSM4(bfr[nf][0], bfr[nf][1], bfr[nf][2], bfr[nf][3],
                      sB + nr * 128 + ((ch ^ (nr & 7)) << 4));
            }
            #pragma unroll
            for (int mf = 0; mf < 4; mf++)
                #pragma unroll
                for (int nf = 0; nf < 4; nf++) {
                    MMA16816(acc[mf][nf*2],   afr[mf], bfr[nf][0], bfr[nf][1]);
                    MMA16816(acc[mf][nf*2+1], afr[mf], bfr[nf][2], bfr[nf][3]);
                }
        }
        __syncthreads();
    }

    #pragma unroll
    for (int mf = 0; mf < 4; mf++) {
        const int r0 = m0 + wm + mf * 16 + (lane >> 2);
        #pragma unroll
        for (int nb = 0; nb < 8; nb++) {
            const int col = n0 + wn + nb * 8 + (lane & 3) * 2;
            float2 bb = *(const float2*)&dec_b[col];
            float2 s0 = { acc[mf][nb][0] + bb.x, acc[mf][nb][1] + bb.y };
            float2 s1 = { acc[mf][nb][2] + bb.x, acc[mf][nb][3] + bb.y };
            *(float2*)&out[(size_t)r0 * VV + col]       = s0;
            *(float2*)&out[(size_t)(r0 + 8) * VV + col] = s1;
        }
    }
}

extern "C" void kernel_launch(void* const* d_in, const int* in_sizes, int n_in,
                              void* d_out, int out_size) {
    const int*   tokens = (const int*)  d_in[0];
    const float* emb    = (const float*)d_in[1];
    const float* W_ih   = (const float*)d_in[2];
    const float* W_hh   = (const float*)d_in[3];
    const float* b_ih   = (const float*)d_in[4];
    const float* b_hh   = (const float*)d_in[5];
    const float* dec_W  = (const float*)d_in[6];
    const float* dec_b  = (const float*)d_in[7];
    float* out = (float*)d_out;

    const size_t dec_elems = (size_t)TT * BB * VV;
    const int write_hidden = ((size_t)out_size >= dec_elems + (size_t)LL*BB*HH) ? 1 : 0;
    float* out_hidden = out + dec_elems;

    cudaFuncSetAttribute(fused_kernel, cudaFuncAttributeMaxDynamicSharedMemorySize, SM_TOTAL);
    cudaFuncSetAttribute(a0_kernel, cudaFuncAttributeMaxDynamicSharedMemorySize, A0_SMEM);

    convW_kernel<<<2048, 256>>>(dec_W);
    {
        dim3 ag(32, 256);
        a0_kernel<<<ag, 256, A0_SMEM>>>(tokens, emb, W_ih, b_ih);
    }
    fused_kernel<<<NCTA + MT * NT, 256, SM_TOTAL>>>(W_ih, W_hh, b_ih, b_hh,
                                                    dec_b, out, out_hidden, write_hidden);
    clr_kernel<<<8, 256>>>();
}

// round 16
// speedup vs baseline: 2.5040x; 1.0143x over previous
#include <cuda_runtime.h>
#include <cuda_fp16.h>
#include <cstdint>
#include <cstddef>

#define TT 256
#define BB 32
#define HH 256
#define LL 4
#define VV 32000
#define HB (HH*BB)
#define NCTA 128

#define DK   256          // plain fp16 GEMM: A=Xhi, B=Whi
#define DBM  128
#define DBN  256
#define DBK  64
#define KITERS (DK/DBK)   // 4
#define MT (8192/DBM)     // 64
#define NT (VV/DBN)       // 125

// ---------------- device scratch ----------------
__device__ float g_h[LL][(size_t)(TT+1)*HB];   // [l][t][k][b]; t=0 row stays zero
__device__ float g_A0[(size_t)TT*HB];          // [t][n][b] = W_ih0 @ emb[tok] + b_ih0
__device__ unsigned g_done[LL][TT+1];          // arrival counters (cleared by clr_kernel)
__device__ __half g_Aext[(size_t)8192*DK];     // [m][k], written by layer-3 RNN CTAs
__device__ __half g_Bext[(size_t)VV*DK];

// ---------------- helpers ----------------
__device__ __forceinline__ uint32_t smem_u32(const void* p) {
    uint32_t a;
    asm("{ .reg .u64 t; cvta.to.shared.u64 t, %1; cvt.u32.u64 %0, t; }" : "=r"(a) : "l"(p));
    return a;
}
#define CP_ASYNC16(dst, src) asm volatile("cp.async.cg.shared.global [%0], [%1], 16;" :: "r"(dst), "l"(src))
#define CP_COMMIT()          asm volatile("cp.async.commit_group;" ::: "memory")
#define CP_WAIT(n)           asm volatile("cp.async.wait_group %0;" :: "n"(n) : "memory")
#define LDSM4(r0,r1,r2,r3,addr) \
    asm volatile("ldmatrix.sync.aligned.m8n8.x4.shared.b16 {%0,%1,%2,%3}, [%4];" \
                 : "=r"(r0),"=r"(r1),"=r"(r2),"=r"(r3) : "r"(addr))
#define MMA16816(d, a, b0, b1) \
    asm volatile("mma.sync.aligned.m16n8k16.row.col.f32.f16.f16.f32 " \
                 "{%0,%1,%2,%3},{%4,%5,%6,%7},{%8,%9},{%0,%1,%2,%3};" \
                 : "+f"((d)[0]),"+f"((d)[1]),"+f"((d)[2]),"+f"((d)[3]) \
                 : "r"((a)[0]),"r"((a)[1]),"r"((a)[2]),"r"((a)[3]), "r"(b0),"r"(b1))

__device__ __forceinline__ void wait32(const unsigned* p) {
    unsigned v;
    do { asm volatile("ld.global.acquire.gpu.u32 %0, [%1];" : "=r"(v) : "l"(p)); } while (v < 32u);
}
__device__ __forceinline__ void arrive_release(unsigned* p) {
    asm volatile("red.release.gpu.global.add.u32 [%0], %1;" :: "l"(p), "r"(1u) : "memory");
}

// f32x2 helpers
__device__ __forceinline__ unsigned long long pk2(float lo, float hi) {
    unsigned long long r;
    asm("mov.b64 %0, {%1, %2};" : "=l"(r) : "r"(__float_as_uint(lo)), "r"(__float_as_uint(hi)));
    return r;
}
__device__ __forceinline__ unsigned long long fma2(unsigned long long a, unsigned long long b,
                                                   unsigned long long c) {
    unsigned long long d;
    asm("fma.rn.f32x2 %0, %1, %2, %3;" : "=l"(d) : "l"(a), "l"(b), "l"(c));
    return d;
}
__device__ __forceinline__ float upks(unsigned long long v) {
    unsigned a, b;
    asm("mov.b64 {%0, %1}, %2;" : "=r"(a), "=r"(b) : "l"(v));
    return __uint_as_float(a) + __uint_as_float(b);
}

// ================= convW =================
__global__ void __launch_bounds__(256) convW_kernel(const float* __restrict__ W) {
    const size_t stride = (size_t)gridDim.x * 256;
    for (size_t e = (size_t)blockIdx.x * 256 + threadIdx.x; e < (size_t)VV * HH; e += stride)
        g_Bext[e] = __float2half(W[e]);
}

// ================= A0 precompute =================
#define A0_SMEM ((8*256 + 256*33 + 8*8*32) * 4)
__global__ void __launch_bounds__(256) a0_kernel(const int* __restrict__ tokens,
                                                 const float* __restrict__ emb,
                                                 const float* __restrict__ W_ih,
                                                 const float* __restrict__ b_ih) {
    extern __shared__ float dsm[];
    float* ws   = dsm;               // [8][256]
    float* xs   = ws + 8*256;        // [256][33]
    float* part = xs + 256*33;       // [8][8][32]
    __shared__ int   tok_s[BB];
    __shared__ float bias_s[8];
    const int t = blockIdx.y, n0 = blockIdx.x * 8, tid = threadIdx.x;

    if (tid < BB) tok_s[tid] = tokens[t*BB + tid];
    if (tid < 8)  bias_s[tid] = b_ih[n0 + tid];
    for (int i = tid; i < 8*256; i += 256) ws[i] = W_ih[(size_t)(n0 + (i >> 8)) * HH + (i & 255)];
    __syncthreads();
    #pragma unroll 4
    for (int r = 0; r < BB; r++) {
        const float* x = emb + (size_t)tok_s[r] * HH;
        xs[tid*33 + r] = x[tid];
    }
    __syncthreads();

    const int wi = tid >> 5, b = tid & 31, kb = wi * 32;
    unsigned long long acc[8];
    #pragma unroll
    for (int j = 0; j < 8; j++) acc[j] = 0ull;
    #pragma unroll
    for (int kk = 0; kk < 32; kk += 2) {
        const int k = kb + kk;
        unsigned long long xv = pk2(xs[k*33 + b], xs[(k+1)*33 + b]);
        #pragma unroll
        for (int j = 0; j < 8; j++)
            acc[j] = fma2(xv, pk2(ws[j*256 + k], ws[j*256 + k + 1]), acc[j]);
    }
    #pragma unroll
    for (int j = 0; j < 8; j++) part[(wi*8 + j)*32 + b] = upks(acc[j]);
    __syncthreads();
    float p = bias_s[wi];
    #pragma unroll
    for (int w2 = 0; w2 < 8; w2++) p += part[(w2*8 + wi)*32 + b];
    g_A0[(size_t)t*HB + (n0 + wi)*BB + b] = p;
}

// ================= clr: reset counters after fused kernel =================
__global__ void __launch_bounds__(256) clr_kernel() {
    unsigned* p = &g_done[0][0];
    const int N = LL * (TT + 1);
    for (int i = blockIdx.x * 256 + threadIdx.x; i < N; i += gridDim.x * 256) p[i] = 0u;
}

// ================= fused RNN + decoder =================
// blocks [0,128): RNN.  blocks [128, 8128): dec tile d = bid-128 (mt-major).
#define STG_A 16384
#define STG_B 32768
#define STG   (STG_A + STG_B)
#define SM_TOTAL (2 * STG)

__device__ __forceinline__ void load_stage(uint32_t smA, uint32_t smB, int kc,
                                           int m0, int n0, int tid) {
    #pragma unroll
    for (int i = 0; i < 4; i++) {
        int l = tid + i * 256;
        int row = l >> 3, c = l & 7;
        const void* src = (const void*)(g_Aext + (size_t)(m0 + row) * DK + kc * DBK + c * 8);
        CP_ASYNC16(smA + row * 128 + ((c ^ (row & 7)) << 4), src);
    }
    #pragma unroll
    for (int i = 0; i < 8; i++) {
        int l = tid + i * 256;
        int row = l >> 3, c = l & 7;
        const void* src = (const void*)(g_Bext + (size_t)(n0 + row) * DK + kc * DBK + c * 8);
        CP_ASYNC16(smB + row * 128 + ((c ^ (row & 7)) << 4), src);
    }
}

__global__ void __launch_bounds__(256, 1) fused_kernel(const float* __restrict__ W_ih,
                                                       const float* __restrict__ W_hh,
                                                       const float* __restrict__ b_ih,
                                                       const float* __restrict__ b_hh,
                                                       const float* __restrict__ dec_b,
                                                       float* __restrict__ out,
                                                       float* out_hidden, int write_hidden) {
    extern __shared__ char smem[];
    const int tid = threadIdx.x;
    const int bid = blockIdx.x;

    if (bid < NCTA) {
        // ================ RNN block ================
        const int l = bid >> 5;
        const int n0 = (bid & 31) * 8;
        float* wih_s  = (float*)smem;            // [8][256]
        float* whh_s  = wih_s + 8*HH;            // [8][256]
        float* part   = whh_s + 8*HH;            // [8][8][32]
        float* bias_s = part + 8*8*BB;           // [8]

        for (int i = tid; i < 8*HH; i += 256) {
            int j = i / HH, k = i % HH;
            wih_s[i] = W_ih[((size_t)l*HH + n0 + j)*HH + k];
            whh_s[i] = W_hh[((size_t)l*HH + n0 + j)*HH + k];
        }
        if (tid < 8) bias_s[tid] = (l == 0 ? 0.f : b_ih[l*HH + n0 + tid]) + b_hh[l*HH + n0 + tid];
        __syncthreads();

        const int wi = tid >> 5, b = tid & 31;
        const int kb = wi * 32;

        for (int t = 0; t < TT; t++) {
            float a0v = 0.f;
            if (l == 0) a0v = g_A0[(size_t)t*HB + (n0 + wi)*BB + b];

            // single-poller waits (parallel, different warps), broadcast by barrier
            if (t > 0 && tid == 0)  wait32(&g_done[l][t]);
            if (l > 0 && tid == 32) wait32(&g_done[l-1][t+1]);
            __syncthreads();

            const float* hp = g_h[l] + (size_t)t * HB;
            unsigned long long acc[8];
            #pragma unroll
            for (int j = 0; j < 8; j++) acc[j] = 0ull;

            if (l == 0) {
                #pragma unroll
                for (int kk = 0; kk < 32; kk += 2) {
                    const int k = kb + kk;
                    unsigned long long hv = pk2(hp[k*BB + b], hp[(k+1)*BB + b]);
                    #pragma unroll
                    for (int j = 0; j < 8; j++) {
                        float2 wh = *(const float2*)&whh_s[j*HH + k];
                        acc[j] = fma2(hv, pk2(wh.x, wh.y), acc[j]);
                    }
                }
            } else {
                const float* xp = g_h[l-1] + (size_t)(t+1) * HB;
                #pragma unroll
                for (int kk = 0; kk < 32; kk += 2) {
                    const int k = kb + kk;
                    unsigned long long hv = pk2(hp[k*BB + b], hp[(k+1)*BB + b]);
                    unsigned long long xv = pk2(xp[k*BB + b], xp[(k+1)*BB + b]);
                    #pragma unroll
                    for (int j = 0; j < 8; j++) {
                        float2 wh = *(const float2*)&whh_s[j*HH + k];
                        float2 wx = *(const float2*)&wih_s[j*HH + k];
                        acc[j] = fma2(hv, pk2(wh.x, wh.y), acc[j]);
                        acc[j] = fma2(xv, pk2(wx.x, wx.y), acc[j]);
                    }
                }
            }
            #pragma unroll
            for (int j = 0; j < 8; j++) part[(wi*8 + j)*32 + b] = upks(acc[j]);
            __syncthreads();
            float p = bias_s[wi] + a0v;
            #pragma unroll
            for (int w2 = 0; w2 < 8; w2++) p += part[(w2*8 + wi)*32 + b];
            float hv = tanhf(p);
            g_h[l][(size_t)(t+1)*HB + (n0 + wi)*BB + b] = hv;
            if (l == LL-1)
                g_Aext[(size_t)(t*BB + b)*DK + (n0 + wi)] = __float2half(hv);
            __syncthreads();        // all h/Aext stores issued; part protected
            if (tid == 0) arrive_release(&g_done[l][t+1]);   // REDG, release folds fence
        }

        if (write_hidden)
            out_hidden[(size_t)l*BB*HH + (size_t)b*HH + (n0 + wi)] =
                g_h[l][(size_t)TT*HB + (n0 + wi)*BB + b];
        return;
    }

    // ================ decoder block ================
    const int d = bid - NCTA;
    const int mt = d / NT, nt = d % NT;
    const int m0 = mt * DBM, n0 = nt * DBN;
    const uint32_t sbase = smem_u32(smem);
    const int wid = tid >> 5, lane = tid & 31;
    const int wm = (wid & 1) * 64;
    const int wn = (wid >> 1) * 64;

    if (tid == 0) wait32(&g_done[LL-1][mt*4 + 4]);
    __syncthreads();

    float acc[4][8][4];
    #pragma unroll
    for (int i = 0; i < 4; i++)
        #pragma unroll
        for (int j = 0; j < 8; j++)
            #pragma unroll
            for (int q = 0; q < 4; q++) acc[i][j][q] = 0.f;

    load_stage(sbase, sbase + STG_A, 0, m0, n0, tid);
    CP_COMMIT();

    #pragma unroll 1
    for (int kc = 0; kc < KITERS; kc++) {
        if (kc + 1 < KITERS) {
            const uint32_t nA = sbase + ((kc + 1) & 1) * STG;
            load_stage(nA, nA + STG_A, kc + 1, m0, n0, tid);
            CP_COMMIT();
            CP_WAIT(1);
        } else {
            CP_WAIT(0);
        }
        __syncthreads();

        const uint32_t sA = sbase + (kc & 1) * STG;
        const uint32_t sB = sA + STG_A;
        #pragma unroll
        for (int k16 = 0; k16 < 4; k16++) {
            uint32_t afr[4][4], bfr[4][4];
            #pragma unroll
            for (int mf = 0; mf < 4; mf++) {
                int rg = wm + mf * 16 + (lane & 15);
                int ch = k16 * 2 + (lane >> 4);
                LDSM4(afr[mf][0], afr[mf][1], afr[mf][2], afr[mf][3],
                      sA + rg * 128 + ((ch ^ (rg & 7)) << 4));
            }
            #pragma unroll
            for (int nf = 0; nf < 4; nf++) {
                int nr = wn + nf * 16 + (lane & 7) + ((lane >> 4) << 3);
                int ch = k16 * 2 + ((lane >> 3) & 1);
                LDSM4(bfr[nf][0], bfr[nf][1], bfr[nf][2], bfr[nf][3],
                      sB + nr * 128 + ((ch ^ (nr & 7)) << 4));
            }
            #pragma unroll
            for (int mf = 0; mf < 4; mf++)
                #pragma unroll
                for (int nf = 0; nf < 4; nf++) {
                    MMA16816(acc[mf][nf*2],   afr[mf], bfr[nf][0], bfr[nf][1]);
                    MMA16816(acc[mf][nf*2+1], afr[mf], bfr[nf][2], bfr[nf][3]);
                }
        }
        __syncthreads();
    }

    #pragma unroll
    for (int mf = 0; mf < 4; mf++) {
        const int r0 = m0 + wm + mf * 16 + (lane >> 2);
        #pragma unroll
        for (int nb = 0; nb < 8; nb++) {
            const int col = n0 + wn + nb * 8 + (lane & 3) * 2;
            float2 bb = *(const float2*)&dec_b[col];
            float2 s0 = { acc[mf][nb][0] + bb.x, acc[mf][nb][1] + bb.y };
            float2 s1 = { acc[mf][nb][2] + bb.x, acc[mf][nb][3] + bb.y };
            *(float2*)&out[(size_t)r0 * VV + col]       = s0;
            *(float2*)&out[(size_t)(r0 + 8) * VV + col] = s1;
        }
    }
}

extern "C" void kernel_launch(void* const* d_in, const int* in_sizes, int n_in,
                              void* d_out, int out_size) {
    const int*   tokens = (const int*)  d_in[0];
    const float* emb    = (const float*)d_in[1];
    const float* W_ih   = (const float*)d_in[2];
    const float* W_hh   = (const float*)d_in[3];
    const float* b_ih   = (const float*)d_in[4];
    const float* b_hh   = (const float*)d_in[5];
    const float* dec_W  = (const float*)d_in[6];
    const float* dec_b  = (const float*)d_in[7];
    float* out = (float*)d_out;

    const size_t dec_elems = (size_t)TT * BB * VV;
    const int write_hidden = ((size_t)out_size >= dec_elems + (size_t)LL*BB*HH) ? 1 : 0;
    float* out_hidden = out + dec_elems;

    cudaFuncSetAttribute(fused_kernel, cudaFuncAttributeMaxDynamicSharedMemorySize, SM_TOTAL);
    cudaFuncSetAttribute(a0_kernel, cudaFuncAttributeMaxDynamicSharedMemorySize, A0_SMEM);

    convW_kernel<<<2048, 256>>>(dec_W);
    {
        dim3 ag(32, 256);
        a0_kernel<<<ag, 256, A0_SMEM>>>(tokens, emb, W_ih, b_ih);
    }
    fused_kernel<<<NCTA + MT * NT, 256, SM_TOTAL>>>(W_ih, W_hh, b_ih, b_hh,
                                                    dec_b, out, out_hidden, write_hidden);
    clr_kernel<<<8, 256>>>();
}

// round 17
// speedup vs baseline: 3.1185x; 1.2454x over previous
#include <cuda_runtime.h>
#include <cuda_fp16.h>
#include <cstdint>
#include <cstddef>

#define TT 256
#define BB 32
#define HH 256
#define LL 4
#define VV 32000
#define HB (HH*BB)

#define NRNN 64             // 4 layers x 16 slice-CTAs
#define NS   16             // neurons per slice

#define DK   256
#define DBM  128
#define DBN  256
#define DBK  64
#define KITERS (DK/DBK)
#define MT (8192/DBM)
#define NT (VV/DBN)

// ---------------- device scratch ----------------
__device__ float g_A0[(size_t)TT*HB];                    // [t][n][b]
__device__ unsigned g_done[LL][TT+1];                    // cleared by clr_kernel
__device__ __half g_hhi[LL][TT+1][BB][HH];               // h hi plane, [b][k]; t=0 stays 0
__device__ __half g_hlo[LL][TT+1][BB][HH];               // h lo plane
__device__ __half g_Whh_hi[(size_t)LL*HH*HH], g_Whh_lo[(size_t)LL*HH*HH];
__device__ __half g_Wih_hi[(size_t)LL*HH*HH], g_Wih_lo[(size_t)LL*HH*HH];
__device__ __half g_Aext[(size_t)8192*DK];               // dec A (= top-layer h_hi)
__device__ __half g_Bext[(size_t)VV*DK];

// ---------------- helpers ----------------
__device__ __forceinline__ uint32_t smem_u32(const void* p) {
    uint32_t a;
    asm("{ .reg .u64 t; cvta.to.shared.u64 t, %1; cvt.u32.u64 %0, t; }" : "=r"(a) : "l"(p));
    return a;
}
#define CP_ASYNC16(dst, src) asm volatile("cp.async.cg.shared.global [%0], [%1], 16;" :: "r"(dst), "l"(src))
#define CP_COMMIT()          asm volatile("cp.async.commit_group;" ::: "memory")
#define CP_WAIT(n)           asm volatile("cp.async.wait_group %0;" :: "n"(n) : "memory")
#define LDSM4(r0,r1,r2,r3,addr) \
    asm volatile("ldmatrix.sync.aligned.m8n8.x4.shared.b16 {%0,%1,%2,%3}, [%4];" \
                 : "=r"(r0),"=r"(r1),"=r"(r2),"=r"(r3) : "r"(addr))
#define MMA16816(d, a, b0, b1) \
    asm volatile("mma.sync.aligned.m16n8k16.row.col.f32.f16.f16.f32 " \
                 "{%0,%1,%2,%3},{%4,%5,%6,%7},{%8,%9},{%0,%1,%2,%3};" \
                 : "+f"((d)[0]),"+f"((d)[1]),"+f"((d)[2]),"+f"((d)[3]) \
                 : "r"((a)[0]),"r"((a)[1]),"r"((a)[2]),"r"((a)[3]), "r"(b0),"r"(b1))

__device__ __forceinline__ void wait16(const unsigned* p) {
    unsigned v;
    do { asm volatile("ld.global.acquire.gpu.u32 %0, [%1];" : "=r"(v) : "l"(p)); } while (v < 16u);
}
__device__ __forceinline__ void arrive_release(unsigned* p) {
    asm volatile("red.release.gpu.global.add.u32 [%0], %1;" :: "l"(p), "r"(1u) : "memory");
}
// f32x2 (a0_kernel)
__device__ __forceinline__ unsigned long long pk2(float lo, float hi) {
    unsigned long long r;
    asm("mov.b64 %0, {%1, %2};" : "=l"(r) : "r"(__float_as_uint(lo)), "r"(__float_as_uint(hi)));
    return r;
}
__device__ __forceinline__ unsigned long long fma2(unsigned long long a, unsigned long long b,
                                                   unsigned long long c) {
    unsigned long long d;
    asm("fma.rn.f32x2 %0, %1, %2, %3;" : "=l"(d) : "l"(a), "l"(b), "l"(c));
    return d;
}
__device__ __forceinline__ float upks(unsigned long long v) {
    unsigned a, b;
    asm("mov.b64 {%0, %1}, %2;" : "=r"(a), "=r"(b) : "l"(v));
    return __uint_as_float(a) + __uint_as_float(b);
}

// ================= conversions =================
__global__ void __launch_bounds__(256) convW_kernel(const float* __restrict__ W) {
    const size_t stride = (size_t)gridDim.x * 256;
    for (size_t e = (size_t)blockIdx.x * 256 + threadIdx.x; e < (size_t)VV * HH; e += stride)
        g_Bext[e] = __float2half(W[e]);
}
__global__ void __launch_bounds__(256) convS_kernel(const float* __restrict__ Whh,
                                                    const float* __restrict__ Wih) {
    const size_t N = (size_t)LL * HH * HH;
    const size_t stride = (size_t)gridDim.x * 256;
    for (size_t e = (size_t)blockIdx.x * 256 + threadIdx.x; e < N; e += stride) {
        float a = Whh[e];
        __half ah = __float2half(a);
        g_Whh_hi[e] = ah; g_Whh_lo[e] = __float2half(a - __half2float(ah));
        float c = Wih[e];
        __half ch = __float2half(c);
        g_Wih_hi[e] = ch; g_Wih_lo[e] = __float2half(c - __half2float(ch));
    }
}
__global__ void __launch_bounds__(256) clr_kernel() {
    unsigned* p = &g_done[0][0];
    const int N = LL * (TT + 1);
    for (int i = blockIdx.x * 256 + threadIdx.x; i < N; i += gridDim.x * 256) p[i] = 0u;
}

// ================= A0 precompute (unchanged) =================
#define A0_SMEM ((8*256 + 256*33 + 8*8*32) * 4)
__global__ void __launch_bounds__(256) a0_kernel(const int* __restrict__ tokens,
                                                 const float* __restrict__ emb,
                                                 const float* __restrict__ W_ih,
                                                 const float* __restrict__ b_ih) {
    extern __shared__ float dsm[];
    float* ws   = dsm;
    float* xs   = ws + 8*256;
    float* part = xs + 256*33;
    __shared__ int   tok_s[BB];
    __shared__ float bias_s[8];
    const int t = blockIdx.y, n0 = blockIdx.x * 8, tid = threadIdx.x;

    if (tid < BB) tok_s[tid] = tokens[t*BB + tid];
    if (tid < 8)  bias_s[tid] = b_ih[n0 + tid];
    for (int i = tid; i < 8*256; i += 256) ws[i] = W_ih[(size_t)(n0 + (i >> 8)) * HH + (i & 255)];
    __syncthreads();
    #pragma unroll 4
    for (int r = 0; r < BB; r++) {
        const float* x = emb + (size_t)tok_s[r] * HH;
        xs[tid*33 + r] = x[tid];
    }
    __syncthreads();
    const int wi = tid >> 5, b = tid & 31, kb = wi * 32;
    unsigned long long acc[8];
    #pragma unroll
    for (int j = 0; j < 8; j++) acc[j] = 0ull;
    #pragma unroll
    for (int kk = 0; kk < 32; kk += 2) {
        const int k = kb + kk;
        unsigned long long xv = pk2(xs[k*33 + b], xs[(k+1)*33 + b]);
        #pragma unroll
        for (int j = 0; j < 8; j++)
            acc[j] = fma2(xv, pk2(ws[j*256 + k], ws[j*256 + k + 1]), acc[j]);
    }
    #pragma unroll
    for (int j = 0; j < 8; j++) part[(wi*8 + j)*32 + b] = upks(acc[j]);
    __syncthreads();
    float p = bias_s[wi];
    #pragma unroll
    for (int w2 = 0; w2 < 8; w2++) p += part[(w2*8 + wi)*32 + b];
    g_A0[(size_t)t*HB + (n0 + wi)*BB + b] = p;
}

// ================= fused: tensor-core RNN + decoder =================
// RNN smem: A 16 slabs x 4KB @0 (64K), B 16 slabs x 2KB @64K (32K), part @96K (16K), bias @112K
#define RA_OFF  0
#define RB_OFF  65536
#define RP_OFF  98304
#define RBI_OFF 114688
#define STG_A 16384
#define STG_B 32768
#define STG   (STG_A + STG_B)
#define SM_TOTAL (114688 + 256)

__device__ __forceinline__ void dec_load_stage(uint32_t smA, uint32_t smB, int kc,
                                               int m0, int n0, int tid) {
    #pragma unroll
    for (int i = 0; i < 4; i++) {
        int l = tid + i * 256;
        int row = l >> 3, c = l & 7;
        const void* src = (const void*)(g_Aext + (size_t)(m0 + row) * DK + kc * DBK + c * 8);
        CP_ASYNC16(smA + row * 128 + ((c ^ (row & 7)) << 4), src);
    }
    #pragma unroll
    for (int i = 0; i < 8; i++) {
        int l = tid + i * 256;
        int row = l >> 3, c = l & 7;
        const void* src = (const void*)(g_Bext + (size_t)(n0 + row) * DK + kc * DBK + c * 8);
        CP_ASYNC16(smB + row * 128 + ((c ^ (row & 7)) << 4), src);
    }
}

__global__ void __launch_bounds__(256, 1) fused_kernel(const float* __restrict__ b_ih,
                                                       const float* __restrict__ b_hh,
                                                       const float* __restrict__ dec_b,
                                                       float* __restrict__ out,
                                                       float* out_hidden, int write_hidden) {
    extern __shared__ char smem[];
    const uint32_t sbase = smem_u32(smem);
    const int tid = threadIdx.x;
    const int bid = blockIdx.x;
    const int wid = tid >> 5, lane = tid & 31;

    if (bid < NRNN) {
        // ================ RNN block: layer l, slice s (16 neurons) ================
        const int l = bid >> 4, s = bid & 15;
        const int n0 = s * NS;
        float* part = (float*)(smem + RP_OFF);     // [8][32][16]
        float* bias = (float*)(smem + RBI_OFF);    // [16]

        // one-time B (weight) smem load: 16 slabs x [16 rows][64 k] fp16, swizzled
        {
            const __half* Wsel[4] = { g_Whh_hi, g_Whh_lo, g_Wih_hi, g_Wih_lo };
            #pragma unroll
            for (int i = 0; i < 8; i++) {
                int idx = tid + i * 256;                 // 0..2047 16B chunks
                int slab = idx >> 7, nr = (idx >> 3) & 15, c = idx & 7;
                const __half* src = Wsel[slab >> 2] +
                    ((size_t)(l*HH + n0 + nr) * HH + (slab & 3) * 64 + c * 8);
                uint4 v = *(const uint4*)src;
                *(uint4*)(smem + RB_OFF + slab*2048 + nr*128 + ((c ^ (nr & 7)) << 4)) = v;
            }
            if (tid < NS)
                bias[tid] = (l == 0 ? 0.f : b_ih[l*HH + n0 + tid]) + b_hh[l*HH + n0 + tid];
        }
        __syncthreads();

        const int ob = tid >> 3;                   // epilogue batch index
        const int on = (tid & 7) * 2;              // epilogue local-n (even)

        for (int t = 0; t < TT; t++) {
            // A0 prefetch (l==0), independent of flags
            float a0v0 = 0.f, a0v1 = 0.f;
            if (l == 0) {
                a0v0 = g_A0[(size_t)t*HB + (n0 + on)*BB + ob];
                a0v1 = g_A0[(size_t)t*HB + (n0 + on + 1)*BB + ob];
            }
            if (t > 0 && tid == 0)  wait16(&g_done[l][t]);
            if (l > 0 && tid == 32) wait16(&g_done[l-1][t+1]);
            __syncthreads();

            // stage A planes: 0:h_hi[l][t] 1:h_lo 2:x_hi=h_hi[l-1][t+1] 3:x_lo
            {
                const __half* pl[4];
                pl[0] = &g_hhi[l][t][0][0];
                pl[1] = &g_hlo[l][t][0][0];
                pl[2] = (l > 0) ? &g_hhi[l-1][t+1][0][0] : pl[0];
                pl[3] = (l > 0) ? &g_hlo[l-1][t+1][0][0] : pl[0];
                const int iters = (l == 0) ? 8 : 16;
                for (int i = 0; i < iters; i++) {
                    int idx = tid + i * 256;
                    int p = idx >> 10, r = (idx >> 5) & 31, ch = idx & 31;
                    const void* src = (const void*)(pl[p] + r * HH + ch * 8);
                    uint32_t dst = sbase + RA_OFF + (p*4 + (ch >> 3))*4096 + r*128 +
                                   (((ch & 7) ^ (r & 7)) << 4);
                    CP_ASYNC16(dst, src);
                }
                CP_COMMIT();
                CP_WAIT(0);
            }
            __syncthreads();

            // MMA: warp w handles products {w, w+8, w+16}
            float acc[2][2][4];
            #pragma unroll
            for (int a = 0; a < 2; a++)
                #pragma unroll
                for (int c = 0; c < 2; c++)
                    #pragma unroll
                    for (int q = 0; q < 4; q++) acc[a][c][q] = 0.f;

            const int nprod = (l == 0) ? 12 : 24;
            #pragma unroll
            for (int pi = 0; pi < 3; pi++) {
                const int p = wid + pi * 8;
                if (p >= nprod) continue;
                const int j = p & 3, g = p >> 2;
                int aslab, bslab;
                if      (g == 0) { aslab = j;      bslab = j; }
                else if (g == 1) { aslab = j + 4;  bslab = j; }
                else if (g == 2) { aslab = j;      bslab = j + 4; }
                else if (g == 3) { aslab = j + 8;  bslab = j + 8; }
                else if (g == 4) { aslab = j + 12; bslab = j + 8; }
                else             { aslab = j + 8;  bslab = j + 12; }
                const uint32_t sA = sbase + RA_OFF + aslab * 4096;
                const uint32_t sB = sbase + RB_OFF + bslab * 2048;
                #pragma unroll
                for (int k16 = 0; k16 < 4; k16++) {
                    uint32_t afr[2][4], bfr[4];
                    #pragma unroll
                    for (int mf = 0; mf < 2; mf++) {
                        int rg = mf * 16 + (lane & 15);
                        int ch = k16 * 2 + (lane >> 4);
                        LDSM4(afr[mf][0], afr[mf][1], afr[mf][2], afr[mf][3],
                              sA + rg * 128 + ((ch ^ (rg & 7)) << 4));
                    }
                    {
                        int nr = (lane & 7) + ((lane >> 4) << 3);
                        int ch = k16 * 2 + ((lane >> 3) & 1);
                        LDSM4(bfr[0], bfr[1], bfr[2], bfr[3],
                              sB + nr * 128 + ((ch ^ (nr & 7)) << 4));
                    }
                    #pragma unroll
                    for (int mf = 0; mf < 2; mf++) {
                        MMA16816(acc[mf][0], afr[mf], bfr[0], bfr[1]);
                        MMA16816(acc[mf][1], afr[mf], bfr[2], bfr[3]);
                    }
                }
            }
            // partials -> smem
            #pragma unroll
            for (int mf = 0; mf < 2; mf++)
                #pragma unroll
                for (int nb = 0; nb < 2; nb++)
                    #pragma unroll
                    for (int q = 0; q < 4; q++) {
                        int m = mf*16 + (lane >> 2) + ((q >> 1) << 3);
                        int n = nb*8 + (lane & 3)*2 + (q & 1);
                        part[wid*512 + m*16 + n] = acc[mf][nb][q];
                    }
            __syncthreads();
            // reduce + epilogue: thread -> (b=ob, n=on,on+1)
            #pragma unroll
            for (int j2 = 0; j2 < 2; j2++) {
                const int n = on + j2;
                float sum = bias[n] + (j2 == 0 ? a0v0 : a0v1);
                #pragma unroll
                for (int w2 = 0; w2 < 8; w2++) sum += part[w2*512 + ob*16 + n];
                float hval = tanhf(sum);
                __half hi = __float2half(hval);
                __half lo = __float2half(hval - __half2float(hi));
                g_hhi[l][t+1][ob][n0 + n] = hi;
                g_hlo[l][t+1][ob][n0 + n] = lo;
                if (l == LL-1)
                    g_Aext[(size_t)(t*BB + ob)*DK + (n0 + n)] = hi;
                if (t == TT-1 && write_hidden)
                    out_hidden[(size_t)l*BB*HH + (size_t)ob*HH + (n0 + n)] = hval;
            }
            __syncthreads();
            if (tid == 0) arrive_release(&g_done[l][t+1]);
        }
        return;
    }

    // ================ decoder block (unchanged except wait count) ================
    const int d = bid - NRNN;
    const int mt = d / NT, nt = d % NT;
    const int m0 = mt * DBM, n0 = nt * DBN;
    const int wm = (wid & 1) * 64;
    const int wn = (wid >> 1) * 64;

    if (tid == 0) wait16(&g_done[LL-1][mt*4 + 4]);
    __syncthreads();

    float acc[4][8][4];
    #pragma unroll
    for (int i = 0; i < 4; i++)
        #pragma unroll
        for (int j = 0; j < 8; j++)
            #pragma unroll
            for (int q = 0; q < 4; q++) acc[i][j][q] = 0.f;

    dec_load_stage(sbase, sbase + STG_A, 0, m0, n0, tid);
    CP_COMMIT();

    #pragma unroll 1
    for (int kc = 0; kc < KITERS; kc++) {
        if (kc + 1 < KITERS) {
            const uint32_t nA = sbase + ((kc + 1) & 1) * STG;
            dec_load_stage(nA, nA + STG_A, kc + 1, m0, n0, tid);
            CP_COMMIT();
            CP_WAIT(1);
        } else {
            CP_WAIT(0);
        }
        __syncthreads();

        const uint32_t sA = sbase + (kc & 1) * STG;
        const uint32_t sB = sA + STG_A;
        #pragma unroll
        for (int k16 = 0; k16 < 4; k16++) {
            uint32_t afr[4][4], bfr[4][4];
            #pragma unroll
            for (int mf = 0; mf < 4; mf++) {
                int rg = wm + mf * 16 + (lane & 15);
                int ch = k16 * 2 + (lane >> 4);
                LDSM4(afr[mf][0], afr[mf][1], afr[mf][2], afr[mf][3],
                      sA + rg * 128 + ((ch ^ (rg & 7)) << 4));
            }
            #pragma unroll
            for (int nf = 0; nf < 4; nf++) {
                int nr = wn + nf * 16 + (lane & 7) + ((lane >> 4) << 3);
                int ch = k16 * 2 + ((lane >> 3) & 1);
                LDSM4(bfr[nf][0], bfr[nf][1], bfr[nf][2], bfr[nf][3],
                      sB + nr * 128 + ((ch ^ (nr & 7)) << 4));
            }
            #pragma unroll
            for (int mf = 0; mf < 4; mf++)
                #pragma unroll
                for (int nf = 0; nf < 4; nf++) {
                    MMA16816(acc[mf][nf*2],   afr[mf], bfr[nf][0], bfr[nf][1]);
                    MMA16816(acc[mf][nf*2+1], afr[mf], bfr[nf][2], bfr[nf][3]);
                }
        }
        __syncthreads();
    }

    #pragma unroll
    for (int mf = 0; mf < 4; mf++) {
        const int r0 = m0 + wm + mf * 16 + (lane >> 2);
        #pragma unroll
        for (int nb = 0; nb < 8; nb++) {
            const int col = n0 + wn + nb * 8 + (lane & 3) * 2;
            float2 bb = *(const float2*)&dec_b[col];
            float2 s0 = { acc[mf][nb][0] + bb.x, acc[mf][nb][1] + bb.y };
            float2 s1 = { acc[mf][nb][2] + bb.x, acc[mf][nb][3] + bb.y };
            *(float2*)&out[(size_t)r0 * VV + col]       = s0;
            *(float2*)&out[(size_t)(r0 + 8) * VV + col] = s1;
        }
    }
}

extern "C" void kernel_launch(void* const* d_in, const int* in_sizes, int n_in,
                              void* d_out, int out_size) {
    const int*   tokens = (const int*)  d_in[0];
    const float* emb    = (const float*)d_in[1];
    const float* W_ih   = (const float*)d_in[2];
    const float* W_hh   = (const float*)d_in[3];
    const float* b_ih   = (const float*)d_in[4];
    const float* b_hh   = (const float*)d_in[5];
    const float* dec_W  = (const float*)d_in[6];
    const float* dec_b  = (const float*)d_in[7];
    float* out = (float*)d_out;

    const size_t dec_elems = (size_t)TT * BB * VV;
    const int write_hidden = ((size_t)out_size >= dec_elems + (size_t)LL*BB*HH) ? 1 : 0;
    float* out_hidden = out + dec_elems;

    cudaFuncSetAttribute(fused_kernel, cudaFuncAttributeMaxDynamicSharedMemorySize, SM_TOTAL);
    cudaFuncSetAttribute(a0_kernel, cudaFuncAttributeMaxDynamicSharedMemorySize, A0_SMEM);

    convW_kernel<<<2048, 256>>>(dec_W);
    convS_kernel<<<256, 256>>>(W_hh, W_ih);
    {
        dim3 ag(32, 256);
        a0_kernel<<<ag, 256, A0_SMEM>>>(tokens, emb, W_ih, b_ih);
    }
    fused_kernel<<<NRNN + MT * NT, 256, SM_TOTAL>>>(b_ih, b_hh, dec_b, out,
                                                    out_hidden, write_hidden);
    clr_kernel<<<8, 256>>>();
}